// round 5
// baseline (speedup 1.0000x reference)
#include <cuda_runtime.h>
#include <cuda_bf16.h>

// ---------------------------------------------------------------------------
// InfoNCE supervised-contrastive loss, fused:
//   k1: detect label width (i64 vs i32) and convert to i32
//   k2: L2-normalize rows, store TRANSPOSED e^T [D][B] (+ zero accumulators)
//   k3: fused GEMM (e @ e^T) + masked LSE via fixed max M = 1/T
//       per_row = log(s_all / s_pos); block atomically accumulates sum/count
//   k4: finalize scalar
// ---------------------------------------------------------------------------

#define NB      8192
#define ND      256
#define BM      64          // rows per block
#define BN      256         // cols per outer col-tile
#define KC      64          // K chunk for B streaming
#define NTHR    256

__device__ float        g_T[ND * NB];   // transposed normalized embeddings [D][B], 8MB
__device__ int          g_lab[NB];
__device__ double       g_sum;
__device__ unsigned int g_cnt;

// ---- packed fp32x2 helpers (Blackwell FFMA2 path, PTX-only) ----------------
__device__ __forceinline__ unsigned long long dup2(float x) {
    unsigned long long r;
    asm("mov.b64 %0, {%1, %1};" : "=l"(r) : "f"(x));
    return r;
}
__device__ __forceinline__ unsigned long long ffma2(unsigned long long a,
                                                    unsigned long long b,
                                                    unsigned long long c) {
    unsigned long long d;
    asm("fma.rn.f32x2 %0, %1, %2, %3;" : "=l"(d) : "l"(a), "l"(b), "l"(c));
    return d;
}
__device__ __forceinline__ float2 unpack2(unsigned long long v) {
    float2 f;
    asm("mov.b64 {%0, %1}, %2;" : "=f"(f.x), "=f"(f.y) : "l"(v));
    return f;
}

// ---------------------------------------------------------------------------
// k1: label conversion. Labels are in [0,1000). If stored as int64 (LE), the
// int32 view is (val,0,val,0,...): all odd words of the first 8192 int32
// (valid bytes in both cases) are zero. For int32 storage, odd words are
// random labels -> essentially impossible to all be zero.
// ---------------------------------------------------------------------------
__global__ void convert_labels_kernel(const int* __restrict__ raw) {
    __shared__ int nz;
    if (threadIdx.x == 0) nz = 0;
    __syncthreads();
    int local = 0;
    for (int i = threadIdx.x; i < NB / 2; i += blockDim.x)
        local |= (raw[2 * i + 1] != 0);
    if (local) atomicOr(&nz, 1);
    __syncthreads();
    const bool is64 = (nz == 0);
    for (int i = threadIdx.x; i < NB; i += blockDim.x)
        g_lab[i] = is64 ? raw[2 * i] : raw[i];
}

// ---------------------------------------------------------------------------
// k2: normalize rows, write transposed  g_T[d][i] = e[i][d] / max(||e_i||,eps)
// ---------------------------------------------------------------------------
__global__ void normalize_kernel(const float* __restrict__ emb) {
    __shared__ float ws[8];
    const int r = blockIdx.x;      // row 0..8191
    const int d = threadIdx.x;     // 0..255
    float v  = emb[r * ND + d];
    float ss = v * v;
    #pragma unroll
    for (int off = 16; off > 0; off >>= 1)
        ss += __shfl_xor_sync(0xffffffffu, ss, off);
    if ((d & 31) == 0) ws[d >> 5] = ss;
    __syncthreads();
    float tot = ws[0] + ws[1] + ws[2] + ws[3] + ws[4] + ws[5] + ws[6] + ws[7];
    float nrm = fmaxf(sqrtf(tot), 1e-12f);
    g_T[d * NB + r] = v / nrm;
    if (d == 0 && r == 0) { g_sum = 0.0; g_cnt = 0u; }
}

// ---------------------------------------------------------------------------
// k3: fused GEMM + masked LSE.
// Block: BM=64 rows x ALL 8192 cols. 256 threads: warp rg (0..7) owns rows
// rg*8..rg*8+7; lane cg (0..31) owns cols {cg*4..+3} and {128+cg*4..+3} of
// each BN=256 col-tile. Microtile 8x8, accumulators packed along row-pairs
// (f32x2). A panel [D][BM] resident in smem; B streamed in [KC][BN] chunks.
// ---------------------------------------------------------------------------
__global__ void __launch_bounds__(NTHR, 1) gemm_lse_kernel() {
    extern __shared__ float smem[];
    float* A_sm = smem;              // [ND][BM]  = 256*64 floats (64KB)
    float* B_sm = smem + ND * BM;    // [KC][BN]  =  64*256 floats (64KB)

    const int tid     = threadIdx.x;
    const int rg      = tid >> 5;    // warp id = row group
    const int cg      = tid & 31;    // lane    = col group
    const int rowbase = blockIdx.x * BM;

    // ---- load A panel (whole D), transposed layout -> contiguous copies ----
    #pragma unroll
    for (int it = 0; it < (ND * BM / 4) / NTHR; ++it) {   // 16 iters
        int f  = tid + NTHR * it;       // float4 index, 0..4095
        int k  = f >> 4;                // 16 float4 per k-row
        int j4 = f & 15;
        reinterpret_cast<float4*>(A_sm)[f] =
            *reinterpret_cast<const float4*>(g_T + k * NB + rowbase + (j4 << 2));
    }

    // ---- row labels for this warp's 8 rows ----
    int labi[8];
    {
        const int4* lp = reinterpret_cast<const int4*>(g_lab + rowbase + rg * 8);
        int4 l0 = lp[0], l1 = lp[1];
        labi[0] = l0.x; labi[1] = l0.y; labi[2] = l0.z; labi[3] = l0.w;
        labi[4] = l1.x; labi[5] = l1.y; labi[6] = l1.z; labi[7] = l1.w;
    }

    float s_all[8], s_pos[8];
    #pragma unroll
    for (int r = 0; r < 8; ++r) { s_all[r] = 0.f; s_pos[r] = 0.f; }

    const float INV_T = 14.285714285714286f;   // 1 / 0.07
    __syncthreads();

    for (int ct = 0; ct < NB / BN; ++ct) {      // 32 col-tiles
        const int colbase = ct * BN;
        const int j1 = colbase + cg * 4;
        const int j2 = colbase + 128 + cg * 4;
        const int4 lj1 = *reinterpret_cast<const int4*>(g_lab + j1);
        const int4 lj2 = *reinterpret_cast<const int4*>(g_lab + j2);

        unsigned long long acc[4][8];
        #pragma unroll
        for (int rp = 0; rp < 4; ++rp)
            #pragma unroll
            for (int c = 0; c < 8; ++c) acc[rp][c] = 0ull;

        for (int kc = 0; kc < ND; kc += KC) {
            __syncthreads();   // protect B_sm from previous chunk's readers
            #pragma unroll
            for (int it = 0; it < (KC * BN / 4) / NTHR; ++it) {   // 16 iters
                int f  = tid + NTHR * it;   // float4 index, 0..4095
                int kk = f >> 6;            // 64 float4 per k-row
                int c4 = f & 63;
                reinterpret_cast<float4*>(B_sm)[f] =
                    *reinterpret_cast<const float4*>(
                        g_T + (kc + kk) * NB + colbase + (c4 << 2));
            }
            __syncthreads();

            #pragma unroll 16
            for (int kk = 0; kk < KC; ++kk) {
                const float* arow = A_sm + kk * BM + rg * 8;   // warp-uniform
                ulonglong2 a0 = *reinterpret_cast<const ulonglong2*>(arow);
                ulonglong2 a1 = *reinterpret_cast<const ulonglong2*>(arow + 4);
                unsigned long long ap[4] = {a0.x, a0.y, a1.x, a1.y};
                const float* brow = B_sm + kk * BN;
                float4 b0 = *reinterpret_cast<const float4*>(brow + cg * 4);
                float4 b1 = *reinterpret_cast<const float4*>(brow + 128 + cg * 4);
                unsigned long long bd[8] = {
                    dup2(b0.x), dup2(b0.y), dup2(b0.z), dup2(b0.w),
                    dup2(b1.x), dup2(b1.y), dup2(b1.z), dup2(b1.w)};
                #pragma unroll
                for (int rp = 0; rp < 4; ++rp)
                    #pragma unroll
                    for (int c = 0; c < 8; ++c)
                        acc[rp][c] = ffma2(ap[rp], bd[c], acc[rp][c]);
            }
        }

        // ---- epilogue: v = exp(sim/T - 1/T); mask diag; route to all/pos ----
        const int jc[8] = {j1, j1 + 1, j1 + 2, j1 + 3, j2, j2 + 1, j2 + 2, j2 + 3};
        const int lj[8] = {lj1.x, lj1.y, lj1.z, lj1.w, lj2.x, lj2.y, lj2.z, lj2.w};
        #pragma unroll
        for (int c = 0; c < 8; ++c) {
            #pragma unroll
            for (int rp = 0; rp < 4; ++rp) {
                float2 x = unpack2(acc[rp][c]);
                const int i0 = rowbase + rg * 8 + 2 * rp;
                float v0 = __expf((x.x - 1.0f) * INV_T);
                float v1 = __expf((x.y - 1.0f) * INV_T);
                if (i0     == jc[c]) v0 = 0.f;      // exclude diagonal
                if (i0 + 1 == jc[c]) v1 = 0.f;
                s_all[2 * rp]     += v0;
                s_all[2 * rp + 1] += v1;
                if (lj[c] == labi[2 * rp])     s_pos[2 * rp]     += v0;
                if (lj[c] == labi[2 * rp + 1]) s_pos[2 * rp + 1] += v1;
            }
        }
    }

    // ---- reduce per-row sums across the 32 lanes of each warp ----
    double lsum = 0.0;
    unsigned int lcnt = 0;
    #pragma unroll
    for (int r = 0; r < 8; ++r) {
        float sa = s_all[r], sp = s_pos[r];
        #pragma unroll
        for (int off = 16; off > 0; off >>= 1) {
            sa += __shfl_xor_sync(0xffffffffu, sa, off);
            sp += __shfl_xor_sync(0xffffffffu, sp, off);
        }
        if (cg == 0 && sp > 0.f) {
            // per_row = all_lse - pos_lse = log(s_all / s_pos)  (shared max)
            lsum += (double)logf(sa / sp);
            lcnt++;
        }
    }
    if (cg == 0) {
        atomicAdd(&g_sum, lsum);
        atomicAdd(&g_cnt, lcnt);
    }
}

// ---------------------------------------------------------------------------
__global__ void finalize_kernel(float* __restrict__ out) {
    unsigned int c = g_cnt;
    out[0] = (c > 0u) ? (float)(g_sum / (double)c) : 0.0f;
}

// ---------------------------------------------------------------------------
extern "C" void kernel_launch(void* const* d_in, const int* in_sizes, int n_in,
                              void* d_out, int out_size) {
    const float* emb = (const float*)d_in[0];
    const int*   lab = (const int*)d_in[1];   // width auto-detected (i64/i32)
    float*       out = (float*)d_out;

    const int smem_bytes = (ND * BM + KC * BN) * (int)sizeof(float);  // 128 KB
    cudaFuncSetAttribute(gemm_lse_kernel,
                         cudaFuncAttributeMaxDynamicSharedMemorySize, smem_bytes);

    convert_labels_kernel<<<1, 1024>>>(lab);
    normalize_kernel<<<NB, ND>>>(emb);
    gemm_lse_kernel<<<NB / BM, NTHR, smem_bytes>>>();
    finalize_kernel<<<1, 1>>>(out);
}

// round 9
// speedup vs baseline: 1.7378x; 1.7378x over previous
#include <cuda_runtime.h>
#include <cuda_bf16.h>
#include <cstdint>

// ---------------------------------------------------------------------------
// InfoNCE supervised-contrastive loss — mma.sync (HMMA) bf16x3 compensated.
// (tcgen05 is unusable: harness compiles via compute_103, no 'a' features.)
//   k1: label width detect (i64/i32) -> i32; zero row accumulators
//   k2: normalize rows; split e = hi(bf16) + lo(bf16), row-major [B][D]
//   k3: 2048 CTAs, 128x256 tile, K=256 in 4 chunks, cp.async double buffer,
//       sim = hi.hiT + hi.loT + lo.hiT via mma.sync.m16n8k16; fused epilogue
//       exp + masked per-row sums -> smem atomics -> global red.
//   k4: per-row log(s_all/s_pos), mean over rows with positives.
// ---------------------------------------------------------------------------

#define NB    8192
#define ND    256
#define BM    128
#define BN    256
#define KC    64
#define NTHR  256

__device__ __nv_bfloat16 g_hi[NB * ND];
__device__ __nv_bfloat16 g_lo[NB * ND];
__device__ int           g_lab[NB];
__device__ float         g_sall[NB];
__device__ float         g_spos[NB];

// ---- smem layout (bytes) ----------------------------------------------------
// stage s (s=0,1) at s*98304:
//   A_hi [128][64]bf16 swizzled : +0      (16 KB)
//   A_lo                        : +16384  (16 KB)
//   B_hi [256][64]bf16 swizzled : +32768  (32 KB)
//   B_lo                        : +65536  (32 KB)
#define STAGE_BYTES 98304
#define LAB_OFF     196608     // 256 ints
#define SALL_OFF    197632     // 128 floats
#define SPOS_OFF    198144     // 128 floats
#define SMEM_TOTAL  198656

// ---- PTX helpers ------------------------------------------------------------
__device__ __forceinline__ uint32_t smem_u32(const void* p) {
    uint32_t a;
    asm("{ .reg .u64 t; cvta.to.shared.u64 t, %1; cvt.u32.u64 %0, t; }" : "=r"(a) : "l"(p));
    return a;
}
__device__ __forceinline__ uint32_t sw128(uint32_t off) {
    return off ^ ((off >> 3) & 0x70);
}
#define CP_ASYNC16(dst, src) \
    asm volatile("cp.async.cg.shared.global [%0], [%1], 16;" :: "r"(dst), "l"(src))
#define CP_COMMIT()  asm volatile("cp.async.commit_group;" ::: "memory")
#define CP_WAIT(n)   asm volatile("cp.async.wait_group %0;" :: "n"(n) : "memory")

__device__ __forceinline__ void ldsm4(uint32_t* r, uint32_t addr) {
    asm volatile("ldmatrix.sync.aligned.m8n8.x4.shared.b16 {%0,%1,%2,%3}, [%4];"
        : "=r"(r[0]), "=r"(r[1]), "=r"(r[2]), "=r"(r[3]) : "r"(addr));
}
__device__ __forceinline__ void mma_bf16(float* d, const uint32_t* a, const uint32_t* b) {
    asm volatile(
        "mma.sync.aligned.m16n8k16.row.col.f32.bf16.bf16.f32 "
        "{%0,%1,%2,%3},{%4,%5,%6,%7},{%8,%9},{%0,%1,%2,%3};"
        : "+f"(d[0]), "+f"(d[1]), "+f"(d[2]), "+f"(d[3])
        : "r"(a[0]), "r"(a[1]), "r"(a[2]), "r"(a[3]), "r"(b[0]), "r"(b[1]));
}

// ---------------------------------------------------------------------------
__global__ void convert_labels_kernel(const int* __restrict__ raw) {
    __shared__ int nz;
    if (threadIdx.x == 0) nz = 0;
    __syncthreads();
    int local = 0;
    for (int i = threadIdx.x; i < NB / 2; i += blockDim.x)
        local |= (raw[2 * i + 1] != 0);
    if (local) atomicOr(&nz, 1);
    __syncthreads();
    const bool is64 = (nz == 0);
    for (int i = threadIdx.x; i < NB; i += blockDim.x) {
        g_lab[i]  = is64 ? raw[2 * i] : raw[i];
        g_sall[i] = 0.f;
        g_spos[i] = 0.f;
    }
}

// ---------------------------------------------------------------------------
__global__ void normalize_kernel(const float* __restrict__ emb) {
    __shared__ float ws[8];
    const int r = blockIdx.x, d = threadIdx.x;
    float v  = emb[r * ND + d];
    float ss = v * v;
    #pragma unroll
    for (int off = 16; off > 0; off >>= 1)
        ss += __shfl_xor_sync(0xffffffffu, ss, off);
    if ((d & 31) == 0) ws[d >> 5] = ss;
    __syncthreads();
    float tot = ws[0] + ws[1] + ws[2] + ws[3] + ws[4] + ws[5] + ws[6] + ws[7];
    float nrm = fmaxf(sqrtf(tot), 1e-12f);
    float e   = v / nrm;
    __nv_bfloat16 hi = __float2bfloat16(e);
    float lo = e - __bfloat162float(hi);
    g_hi[r * ND + d] = hi;
    g_lo[r * ND + d] = __float2bfloat16(lo);
}

// ---------------------------------------------------------------------------
// Stage load: 6144 x 16B cp.async (24 per thread).
__device__ __forceinline__ void load_stage(uint32_t sbase, int kc,
                                           int rowbase, int colbase) {
    const int tid = threadIdx.x;
    #pragma unroll
    for (int i = 0; i < 24; ++i) {
        const int g = tid + NTHR * i;
        const __nv_bfloat16* src;
        uint32_t dst;
        if (g < 2048) {                    // A: hi then lo
            const int half = g >> 10, r = (g >> 3) & 127, k16 = g & 7;
            src = (half ? g_lo : g_hi) + (rowbase + r) * ND + kc * KC + k16 * 8;
            dst = sbase + half * 16384 + sw128(r * 128 + k16 * 16);
        } else {                           // B: hi then lo
            const int b = g - 2048;
            const int half = b >> 11, r = (b >> 3) & 255, k16 = b & 7;
            src = (half ? g_lo : g_hi) + (colbase + r) * ND + kc * KC + k16 * 8;
            dst = sbase + 32768 + half * 32768 + sw128(r * 128 + k16 * 16);
        }
        CP_ASYNC16(dst, src);
    }
}

// ---------------------------------------------------------------------------
__global__ void __launch_bounds__(NTHR, 1) gemm_lse_kernel() {
    extern __shared__ char smem[];
    const uint32_t sb = smem_u32(smem);
    int*   lab_sm  = (int*)(smem + LAB_OFF);
    float* sall_sm = (float*)(smem + SALL_OFF);
    float* spos_sm = (float*)(smem + SPOS_OFF);

    const int tid  = threadIdx.x;
    const int wid  = tid >> 5, lane = tid & 31;
    const int wm   = wid >> 2;           // 0..1  (64 rows each)
    const int wn   = wid & 3;            // 0..3  (64 cols each)
    const int rowbase = (int)(blockIdx.x >> 5) * BM;   // 64 row tiles
    const int colbase = (int)(blockIdx.x & 31) * BN;   // 32 col tiles

    // prologue: labels + smem accumulators + first stage
    lab_sm[tid] = g_lab[colbase + tid];
    if (tid < BM) { sall_sm[tid] = 0.f; spos_sm[tid] = 0.f; }
    load_stage(sb, 0, rowbase, colbase);
    CP_COMMIT();

    // ldmatrix lane addressing constants
    const uint32_t a_row = ((lane >> 3) & 1) * 8 + (lane & 7);
    const uint32_t a_kb  = ((lane >> 4) & 1) * 16;
    const uint32_t b_row = ((lane >> 4) & 1) * 8 + (lane & 7);
    const uint32_t b_kb  = ((lane >> 3) & 1) * 16;
    const uint32_t xm    = (uint32_t)(lane & 7) << 4;
    const uint32_t arow_off = (wm * 64 + a_row) * 128;
    const uint32_t brow_off = (wn * 64 + b_row) * 128;

    float acc[4][8][4];
    #pragma unroll
    for (int mt = 0; mt < 4; ++mt)
        #pragma unroll
        for (int nt = 0; nt < 8; ++nt)
            #pragma unroll
            for (int e = 0; e < 4; ++e) acc[mt][nt][e] = 0.f;

    for (int kc = 0; kc < ND / KC; ++kc) {           // 4 chunks
        if (kc < 3) {
            load_stage(sb + ((kc + 1) & 1) * STAGE_BYTES, kc + 1, rowbase, colbase);
            CP_COMMIT();
            CP_WAIT(1);
        } else {
            CP_WAIT(0);
        }
        __syncthreads();

        const uint32_t st = sb + (kc & 1) * STAGE_BYTES;
        #pragma unroll
        for (int k16 = 0; k16 < 4; ++k16) {
            const uint32_t akx = ((uint32_t)(k16 * 32) + a_kb) ^ xm;
            const uint32_t bkx = ((uint32_t)(k16 * 32) + b_kb) ^ xm;
            uint32_t ah[4][4], al[4][4], bh[4][4], bl[4][4];
            #pragma unroll
            for (int mt = 0; mt < 4; ++mt) {
                ldsm4(ah[mt], st +         arow_off + mt * 2048 + akx);
                ldsm4(al[mt], st + 16384 + arow_off + mt * 2048 + akx);
            }
            #pragma unroll
            for (int p = 0; p < 4; ++p) {
                ldsm4(bh[p], st + 32768 + brow_off + p * 2048 + bkx);
                ldsm4(bl[p], st + 65536 + brow_off + p * 2048 + bkx);
            }
            #pragma unroll
            for (int mt = 0; mt < 4; ++mt)
                #pragma unroll
                for (int nt = 0; nt < 8; ++nt)
                    mma_bf16(acc[mt][nt], ah[mt], &bh[nt >> 1][(nt & 1) * 2]);
            #pragma unroll
            for (int mt = 0; mt < 4; ++mt)
                #pragma unroll
                for (int nt = 0; nt < 8; ++nt)
                    mma_bf16(acc[mt][nt], ah[mt], &bl[nt >> 1][(nt & 1) * 2]);
            #pragma unroll
            for (int mt = 0; mt < 4; ++mt)
                #pragma unroll
                for (int nt = 0; nt < 8; ++nt)
                    mma_bf16(acc[mt][nt], al[mt], &bh[nt >> 1][(nt & 1) * 2]);
        }
        __syncthreads();
    }

    // ================= fused epilogue =================
    const float INV_T = 14.285714285714286f;
    // column labels + global col indices for this thread (16 cols)
    int labc[16];
    #pragma unroll
    for (int nt = 0; nt < 8; ++nt) {
        const int cl = wn * 64 + nt * 8 + 2 * (lane & 3);
        labc[2 * nt]     = lab_sm[cl];
        labc[2 * nt + 1] = lab_sm[cl + 1];
    }
    int rlab[8];
    #pragma unroll
    for (int mt = 0; mt < 4; ++mt) {
        const int r0 = rowbase + wm * 64 + mt * 16 + (lane >> 2);
        rlab[2 * mt]     = g_lab[r0];
        rlab[2 * mt + 1] = g_lab[r0 + 8];
    }

    float psall[8], pspos[8];
    #pragma unroll
    for (int r = 0; r < 8; ++r) { psall[r] = 0.f; pspos[r] = 0.f; }

    #pragma unroll
    for (int mt = 0; mt < 4; ++mt) {
        const int rg0 = rowbase + wm * 64 + mt * 16 + (lane >> 2);
        const int rg1 = rg0 + 8;
        #pragma unroll
        for (int nt = 0; nt < 8; ++nt) {
            const int cg0 = colbase + wn * 64 + nt * 8 + 2 * (lane & 3);
            const int cg1 = cg0 + 1;
            const float* a4 = acc[mt][nt];
            float v0 = __expf(fmaf(a4[0], INV_T, -INV_T));
            float v1 = __expf(fmaf(a4[1], INV_T, -INV_T));
            float v2 = __expf(fmaf(a4[2], INV_T, -INV_T));
            float v3 = __expf(fmaf(a4[3], INV_T, -INV_T));
            if (rg0 == cg0) v0 = 0.f;
            if (rg0 == cg1) v1 = 0.f;
            if (rg1 == cg0) v2 = 0.f;
            if (rg1 == cg1) v3 = 0.f;
            psall[2 * mt]     += v0 + v1;
            psall[2 * mt + 1] += v2 + v3;
            if (labc[2 * nt]     == rlab[2 * mt])     pspos[2 * mt]     += v0;
            if (labc[2 * nt + 1] == rlab[2 * mt])     pspos[2 * mt]     += v1;
            if (labc[2 * nt]     == rlab[2 * mt + 1]) pspos[2 * mt + 1] += v2;
            if (labc[2 * nt + 1] == rlab[2 * mt + 1]) pspos[2 * mt + 1] += v3;
        }
    }
    #pragma unroll
    for (int mt = 0; mt < 4; ++mt) {
        const int rl0 = wm * 64 + mt * 16 + (lane >> 2);
        atomicAdd(&sall_sm[rl0],     psall[2 * mt]);
        atomicAdd(&sall_sm[rl0 + 8], psall[2 * mt + 1]);
        atomicAdd(&spos_sm[rl0],     pspos[2 * mt]);
        atomicAdd(&spos_sm[rl0 + 8], pspos[2 * mt + 1]);
    }
    __syncthreads();
    if (tid < BM) {
        atomicAdd(&g_sall[rowbase + tid], sall_sm[tid]);
        atomicAdd(&g_spos[rowbase + tid], spos_sm[tid]);
    }
}

// ---------------------------------------------------------------------------
__global__ void finalize_kernel(float* __restrict__ out) {
    __shared__ double ssum[32];
    __shared__ int    scnt[32];
    const int tid = threadIdx.x, w = tid >> 5, l = tid & 31;
    double ls = 0.0; int lc = 0;
    for (int r = tid; r < NB; r += 1024) {
        float sp = g_spos[r];
        if (sp > 0.f) { ls += log((double)g_sall[r] / (double)sp); lc++; }
    }
    #pragma unroll
    for (int off = 16; off > 0; off >>= 1) {
        ls += __shfl_xor_sync(0xffffffffu, ls, off);
        lc += __shfl_xor_sync(0xffffffffu, lc, off);
    }
    if (l == 0) { ssum[w] = ls; scnt[w] = lc; }
    __syncthreads();
    if (w == 0) {
        ls = ssum[l]; lc = scnt[l];
        #pragma unroll
        for (int off = 16; off > 0; off >>= 1) {
            ls += __shfl_xor_sync(0xffffffffu, ls, off);
            lc += __shfl_xor_sync(0xffffffffu, lc, off);
        }
        if (l == 0) out[0] = (lc > 0) ? (float)(ls / (double)lc) : 0.0f;
    }
}

// ---------------------------------------------------------------------------
extern "C" void kernel_launch(void* const* d_in, const int* in_sizes, int n_in,
                              void* d_out, int out_size) {
    const float* emb = (const float*)d_in[0];
    const int*   lab = (const int*)d_in[1];
    float*       out = (float*)d_out;

    cudaFuncSetAttribute(gemm_lse_kernel,
                         cudaFuncAttributeMaxDynamicSharedMemorySize, SMEM_TOTAL);

    convert_labels_kernel<<<1, 1024>>>(lab);
    normalize_kernel<<<NB, ND>>>(emb);
    gemm_lse_kernel<<<(NB / BM) * (NB / BN), NTHR, SMEM_TOTAL>>>();
    finalize_kernel<<<1, 1024>>>(out);
}

// round 10
// speedup vs baseline: 1.7393x; 1.0009x over previous
#include <cuda_runtime.h>
#include <cuda_bf16.h>
#include <cstdint>

// ---------------------------------------------------------------------------
// InfoNCE supervised-contrastive loss — mma.sync (HMMA) bf16x3 compensated.
// (tcgen05 is unusable: harness compiles via compute_103, no 'a' features.)
//   k1: label width detect (i64/i32) -> i32; zero row accumulators
//   k2: normalize rows; split e = hi(bf16) + lo(bf16), row-major [B][D]
//   k3: 2048 CTAs, 128x256 tile, K=256 in 4 chunks, cp.async double buffer,
//       sim = hi.hiT + hi.loT + lo.hiT via mma.sync.m16n8k16; fused epilogue
//       exp + masked per-row sums -> smem atomics -> global red.
//   k4: per-row log(s_all/s_pos), mean over rows with positives.
// ---------------------------------------------------------------------------

#define NB    8192
#define ND    256
#define BM    128
#define BN    256
#define KC    64
#define NTHR  256

__device__ __nv_bfloat16 g_hi[NB * ND];
__device__ __nv_bfloat16 g_lo[NB * ND];
__device__ int           g_lab[NB];
__device__ float         g_sall[NB];
__device__ float         g_spos[NB];

// ---- smem layout (bytes) ----------------------------------------------------
// stage s (s=0,1) at s*98304:
//   A_hi [128][64]bf16 swizzled : +0      (16 KB)
//   A_lo                        : +16384  (16 KB)
//   B_hi [256][64]bf16 swizzled : +32768  (32 KB)
//   B_lo                        : +65536  (32 KB)
#define STAGE_BYTES 98304
#define LAB_OFF     196608     // 256 ints
#define SALL_OFF    197632     // 128 floats
#define SPOS_OFF    198144     // 128 floats
#define SMEM_TOTAL  198656

// ---- PTX helpers ------------------------------------------------------------
__device__ __forceinline__ uint32_t smem_u32(const void* p) {
    uint32_t a;
    asm("{ .reg .u64 t; cvta.to.shared.u64 t, %1; cvt.u32.u64 %0, t; }" : "=r"(a) : "l"(p));
    return a;
}
__device__ __forceinline__ uint32_t sw128(uint32_t off) {
    return off ^ ((off >> 3) & 0x70);
}
#define CP_ASYNC16(dst, src) \
    asm volatile("cp.async.cg.shared.global [%0], [%1], 16;" :: "r"(dst), "l"(src))
#define CP_COMMIT()  asm volatile("cp.async.commit_group;" ::: "memory")
#define CP_WAIT(n)   asm volatile("cp.async.wait_group %0;" :: "n"(n) : "memory")

__device__ __forceinline__ void ldsm4(uint32_t* r, uint32_t addr) {
    asm volatile("ldmatrix.sync.aligned.m8n8.x4.shared.b16 {%0,%1,%2,%3}, [%4];"
        : "=r"(r[0]), "=r"(r[1]), "=r"(r[2]), "=r"(r[3]) : "r"(addr));
}
__device__ __forceinline__ void mma_bf16(float* d, const uint32_t* a, const uint32_t* b) {
    asm volatile(
        "mma.sync.aligned.m16n8k16.row.col.f32.bf16.bf16.f32 "
        "{%0,%1,%2,%3},{%4,%5,%6,%7},{%8,%9},{%0,%1,%2,%3};"
        : "+f"(d[0]), "+f"(d[1]), "+f"(d[2]), "+f"(d[3])
        : "r"(a[0]), "r"(a[1]), "r"(a[2]), "r"(a[3]), "r"(b[0]), "r"(b[1]));
}

// ---------------------------------------------------------------------------
__global__ void convert_labels_kernel(const int* __restrict__ raw) {
    __shared__ int nz;
    if (threadIdx.x == 0) nz = 0;
    __syncthreads();
    int local = 0;
    for (int i = threadIdx.x; i < NB / 2; i += blockDim.x)
        local |= (raw[2 * i + 1] != 0);
    if (local) atomicOr(&nz, 1);
    __syncthreads();
    const bool is64 = (nz == 0);
    for (int i = threadIdx.x; i < NB; i += blockDim.x) {
        g_lab[i]  = is64 ? raw[2 * i] : raw[i];
        g_sall[i] = 0.f;
        g_spos[i] = 0.f;
    }
}

// ---------------------------------------------------------------------------
__global__ void normalize_kernel(const float* __restrict__ emb) {
    __shared__ float ws[8];
    const int r = blockIdx.x, d = threadIdx.x;
    float v  = emb[r * ND + d];
    float ss = v * v;
    #pragma unroll
    for (int off = 16; off > 0; off >>= 1)
        ss += __shfl_xor_sync(0xffffffffu, ss, off);
    if ((d & 31) == 0) ws[d >> 5] = ss;
    __syncthreads();
    float tot = ws[0] + ws[1] + ws[2] + ws[3] + ws[4] + ws[5] + ws[6] + ws[7];
    float nrm = fmaxf(sqrtf(tot), 1e-12f);
    float e   = v / nrm;
    __nv_bfloat16 hi = __float2bfloat16(e);
    float lo = e - __bfloat162float(hi);
    g_hi[r * ND + d] = hi;
    g_lo[r * ND + d] = __float2bfloat16(lo);
}

// ---------------------------------------------------------------------------
// Stage load: 6144 x 16B cp.async (24 per thread).
__device__ __forceinline__ void load_stage(uint32_t sbase, int kc,
                                           int rowbase, int colbase) {
    const int tid = threadIdx.x;
    #pragma unroll
    for (int i = 0; i < 24; ++i) {
        const int g = tid + NTHR * i;
        const __nv_bfloat16* src;
        uint32_t dst;
        if (g < 2048) {                    // A: hi then lo
            const int half = g >> 10, r = (g >> 3) & 127, k16 = g & 7;
            src = (half ? g_lo : g_hi) + (rowbase + r) * ND + kc * KC + k16 * 8;
            dst = sbase + half * 16384 + sw128(r * 128 + k16 * 16);
        } else {                           // B: hi then lo
            const int b = g - 2048;
            const int half = b >> 11, r = (b >> 3) & 255, k16 = b & 7;
            src = (half ? g_lo : g_hi) + (colbase + r) * ND + kc * KC + k16 * 8;
            dst = sbase + 32768 + half * 32768 + sw128(r * 128 + k16 * 16);
        }
        CP_ASYNC16(dst, src);
    }
}

// ---------------------------------------------------------------------------
__global__ void __launch_bounds__(NTHR, 1) gemm_lse_kernel() {
    extern __shared__ char smem[];
    const uint32_t sb = smem_u32(smem);
    int*   lab_sm  = (int*)(smem + LAB_OFF);
    float* sall_sm = (float*)(smem + SALL_OFF);
    float* spos_sm = (float*)(smem + SPOS_OFF);

    const int tid  = threadIdx.x;
    const int wid  = tid >> 5, lane = tid & 31;
    const int wm   = wid >> 2;           // 0..1  (64 rows each)
    const int wn   = wid & 3;            // 0..3  (64 cols each)
    const int rowbase = (int)(blockIdx.x >> 5) * BM;   // 64 row tiles
    const int colbase = (int)(blockIdx.x & 31) * BN;   // 32 col tiles

    // prologue: labels + smem accumulators + first stage
    lab_sm[tid] = g_lab[colbase + tid];
    if (tid < BM) { sall_sm[tid] = 0.f; spos_sm[tid] = 0.f; }
    load_stage(sb, 0, rowbase, colbase);
    CP_COMMIT();

    // ldmatrix lane addressing constants
    const uint32_t a_row = ((lane >> 3) & 1) * 8 + (lane & 7);
    const uint32_t a_kb  = ((lane >> 4) & 1) * 16;
    const uint32_t b_row = ((lane >> 4) & 1) * 8 + (lane & 7);
    const uint32_t b_kb  = ((lane >> 3) & 1) * 16;
    const uint32_t xm    = (uint32_t)(lane & 7) << 4;
    const uint32_t arow_off = (wm * 64 + a_row) * 128;
    const uint32_t brow_off = (wn * 64 + b_row) * 128;

    float acc[4][8][4];
    #pragma unroll
    for (int mt = 0; mt < 4; ++mt)
        #pragma unroll
        for (int nt = 0; nt < 8; ++nt)
            #pragma unroll
            for (int e = 0; e < 4; ++e) acc[mt][nt][e] = 0.f;

    for (int kc = 0; kc < ND / KC; ++kc) {           // 4 chunks
        if (kc < 3) {
            load_stage(sb + ((kc + 1) & 1) * STAGE_BYTES, kc + 1, rowbase, colbase);
            CP_COMMIT();
            CP_WAIT(1);
        } else {
            CP_WAIT(0);
        }
        __syncthreads();

        const uint32_t st = sb + (kc & 1) * STAGE_BYTES;
        #pragma unroll
        for (int k16 = 0; k16 < 4; ++k16) {
            const uint32_t akx = ((uint32_t)(k16 * 32) + a_kb) ^ xm;
            const uint32_t bkx = ((uint32_t)(k16 * 32) + b_kb) ^ xm;
            uint32_t ah[4][4], al[4][4], bh[4][4], bl[4][4];
            #pragma unroll
            for (int mt = 0; mt < 4; ++mt) {
                ldsm4(ah[mt], st +         arow_off + mt * 2048 + akx);
                ldsm4(al[mt], st + 16384 + arow_off + mt * 2048 + akx);
            }
            #pragma unroll
            for (int p = 0; p < 4; ++p) {
                ldsm4(bh[p], st + 32768 + brow_off + p * 2048 + bkx);
                ldsm4(bl[p], st + 65536 + brow_off + p * 2048 + bkx);
            }
            #pragma unroll
            for (int mt = 0; mt < 4; ++mt)
                #pragma unroll
                for (int nt = 0; nt < 8; ++nt)
                    mma_bf16(acc[mt][nt], ah[mt], &bh[nt >> 1][(nt & 1) * 2]);
            #pragma unroll
            for (int mt = 0; mt < 4; ++mt)
                #pragma unroll
                for (int nt = 0; nt < 8; ++nt)
                    mma_bf16(acc[mt][nt], ah[mt], &bl[nt >> 1][(nt & 1) * 2]);
            #pragma unroll
            for (int mt = 0; mt < 4; ++mt)
                #pragma unroll
                for (int nt = 0; nt < 8; ++nt)
                    mma_bf16(acc[mt][nt], al[mt], &bh[nt >> 1][(nt & 1) * 2]);
        }
        __syncthreads();
    }

    // ================= fused epilogue =================
    const float INV_T = 14.285714285714286f;
    // column labels + global col indices for this thread (16 cols)
    int labc[16];
    #pragma unroll
    for (int nt = 0; nt < 8; ++nt) {
        const int cl = wn * 64 + nt * 8 + 2 * (lane & 3);
        labc[2 * nt]     = lab_sm[cl];
        labc[2 * nt + 1] = lab_sm[cl + 1];
    }
    int rlab[8];
    #pragma unroll
    for (int mt = 0; mt < 4; ++mt) {
        const int r0 = rowbase + wm * 64 + mt * 16 + (lane >> 2);
        rlab[2 * mt]     = g_lab[r0];
        rlab[2 * mt + 1] = g_lab[r0 + 8];
    }

    float psall[8], pspos[8];
    #pragma unroll
    for (int r = 0; r < 8; ++r) { psall[r] = 0.f; pspos[r] = 0.f; }

    #pragma unroll
    for (int mt = 0; mt < 4; ++mt) {
        const int rg0 = rowbase + wm * 64 + mt * 16 + (lane >> 2);
        const int rg1 = rg0 + 8;
        #pragma unroll
        for (int nt = 0; nt < 8; ++nt) {
            const int cg0 = colbase + wn * 64 + nt * 8 + 2 * (lane & 3);
            const int cg1 = cg0 + 1;
            const float* a4 = acc[mt][nt];
            float v0 = __expf(fmaf(a4[0], INV_T, -INV_T));
            float v1 = __expf(fmaf(a4[1], INV_T, -INV_T));
            float v2 = __expf(fmaf(a4[2], INV_T, -INV_T));
            float v3 = __expf(fmaf(a4[3], INV_T, -INV_T));
            if (rg0 == cg0) v0 = 0.f;
            if (rg0 == cg1) v1 = 0.f;
            if (rg1 == cg0) v2 = 0.f;
            if (rg1 == cg1) v3 = 0.f;
            psall[2 * mt]     += v0 + v1;
            psall[2 * mt + 1] += v2 + v3;
            if (labc[2 * nt]     == rlab[2 * mt])     pspos[2 * mt]     += v0;
            if (labc[2 * nt + 1] == rlab[2 * mt])     pspos[2 * mt]     += v1;
            if (labc[2 * nt]     == rlab[2 * mt + 1]) pspos[2 * mt + 1] += v2;
            if (labc[2 * nt + 1] == rlab[2 * mt + 1]) pspos[2 * mt + 1] += v3;
        }
    }
    #pragma unroll
    for (int mt = 0; mt < 4; ++mt) {
        const int rl0 = wm * 64 + mt * 16 + (lane >> 2);
        atomicAdd(&sall_sm[rl0],     psall[2 * mt]);
        atomicAdd(&sall_sm[rl0 + 8], psall[2 * mt + 1]);
        atomicAdd(&spos_sm[rl0],     pspos[2 * mt]);
        atomicAdd(&spos_sm[rl0 + 8], pspos[2 * mt + 1]);
    }
    __syncthreads();
    if (tid < BM) {
        atomicAdd(&g_sall[rowbase + tid], sall_sm[tid]);
        atomicAdd(&g_spos[rowbase + tid], spos_sm[tid]);
    }
}

// ---------------------------------------------------------------------------
__global__ void finalize_kernel(float* __restrict__ out) {
    __shared__ double ssum[32];
    __shared__ int    scnt[32];
    const int tid = threadIdx.x, w = tid >> 5, l = tid & 31;
    double ls = 0.0; int lc = 0;
    for (int r = tid; r < NB; r += 1024) {
        float sp = g_spos[r];
        if (sp > 0.f) { ls += log((double)g_sall[r] / (double)sp); lc++; }
    }
    #pragma unroll
    for (int off = 16; off > 0; off >>= 1) {
        ls += __shfl_xor_sync(0xffffffffu, ls, off);
        lc += __shfl_xor_sync(0xffffffffu, lc, off);
    }
    if (l == 0) { ssum[w] = ls; scnt[w] = lc; }
    __syncthreads();
    if (w == 0) {
        ls = ssum[l]; lc = scnt[l];
        #pragma unroll
        for (int off = 16; off > 0; off >>= 1) {
            ls += __shfl_xor_sync(0xffffffffu, ls, off);
            lc += __shfl_xor_sync(0xffffffffu, lc, off);
        }
        if (l == 0) out[0] = (lc > 0) ? (float)(ls / (double)lc) : 0.0f;
    }
}

// ---------------------------------------------------------------------------
extern "C" void kernel_launch(void* const* d_in, const int* in_sizes, int n_in,
                              void* d_out, int out_size) {
    const float* emb = (const float*)d_in[0];
    const int*   lab = (const int*)d_in[1];
    float*       out = (float*)d_out;

    cudaFuncSetAttribute(gemm_lse_kernel,
                         cudaFuncAttributeMaxDynamicSharedMemorySize, SMEM_TOTAL);

    convert_labels_kernel<<<1, 1024>>>(lab);
    normalize_kernel<<<NB, ND>>>(emb);
    gemm_lse_kernel<<<(NB / BM) * (NB / BN), NTHR, SMEM_TOTAL>>>();
    finalize_kernel<<<1, 1024>>>(out);
}

// round 11
// speedup vs baseline: 2.3418x; 1.3464x over previous
#include <cuda_runtime.h>
#include <cuda_bf16.h>
#include <cstdint>

// ---------------------------------------------------------------------------
// InfoNCE supervised-contrastive loss — HMMA bf16x3 + cp.async.bulk stages.
//   k1: label width detect (i64/i32) -> i32; zero row accumulators
//   k2: normalize rows; split e = hi(bf16)+lo(bf16); store K-chunk-major,
//       PRE-SWIZZLED (SW128) so a linear bulk copy lands MMA-ready in smem.
//   k3: 2048 CTAs, 128x256 tile, K=256 in 4 chunks, 2-stage pipeline fed by
//       cp.async.bulk (UBLKCP) + mbarrier expect_tx; sim = hi.hiT + hi.loT +
//       lo.hiT via mma.sync.m16n8k16; fused exp epilogue, per-row sums.
//   k4: per-row __logf(s_all/s_pos), mean over rows with positives.
// ---------------------------------------------------------------------------

#define NB    8192
#define ND    256
#define BM    128
#define BN    256
#define KC    64
#define NTHR  256
#define CHUNK_ELEMS (NB * KC)          // elements per K-chunk plane

__device__ __align__(1024) __nv_bfloat16 g_hi[NB * ND];  // [4][8192][64] swizzled
__device__ __align__(1024) __nv_bfloat16 g_lo[NB * ND];
__device__ int   g_lab[NB];
__device__ float g_sall[NB];
__device__ float g_spos[NB];

// ---- smem layout (bytes) ----------------------------------------------------
// stage s (s=0,1) at s*98304:
//   A_hi [128][64]bf16 swizzled : +0      (16 KB)
//   A_lo                        : +16384  (16 KB)
//   B_hi [256][64]bf16 swizzled : +32768  (32 KB)
//   B_lo                        : +65536  (32 KB)
#define STAGE_BYTES 98304
#define LAB_OFF     196608     // 256 ints
#define SALL_OFF    197632     // 128 floats
#define SPOS_OFF    198144     // 128 floats
#define CTRL_OFF    198656     // 2 mbarriers
#define SMEM_TOTAL  198784

// ---- PTX helpers ------------------------------------------------------------
__device__ __forceinline__ uint32_t smem_u32(const void* p) {
    uint32_t a;
    asm("{ .reg .u64 t; cvta.to.shared.u64 t, %1; cvt.u32.u64 %0, t; }" : "=r"(a) : "l"(p));
    return a;
}
__device__ __forceinline__ uint32_t sw128(uint32_t off) {
    return off ^ ((off >> 3) & 0x70);   // permutes 16B granules within a 128B row
}
#define MBAR_INIT(addr, cnt) \
    asm volatile("mbarrier.init.shared.b64 [%0], %1;" :: "r"(addr), "r"((uint32_t)(cnt)) : "memory")
#define MBAR_EXPECT_TX(addr, bytes) \
    asm volatile("mbarrier.arrive.expect_tx.shared.b64 _, [%0], %1;" :: "r"(addr), "r"((uint32_t)(bytes)) : "memory")
#define MBAR_WAIT(addr, parity) do {                                                   \
    asm volatile("{\n\t.reg .pred P1;\n\t"                                             \
        "WAIT_LP_%=:\n\t"                                                              \
        "mbarrier.try_wait.parity.acquire.cta.shared::cta.b64 P1, [%0], %1, 0x989680;\n\t" \
        "@P1 bra.uni WAIT_DN_%=;\n\t"                                                  \
        "bra.uni WAIT_LP_%=;\n\t"                                                      \
        "WAIT_DN_%=:\n\t}"                                                             \
        :: "r"(addr), "r"((uint32_t)(parity)) : "memory");                             \
} while (0)
__device__ __forceinline__ void bulk_ld(uint32_t dst, const void* src,
                                        uint32_t bytes, uint32_t mbar) {
    asm volatile(
        "cp.async.bulk.shared::cta.global.mbarrier::complete_tx::bytes [%0], [%1], %2, [%3];"
        :: "r"(dst), "l"(src), "r"(bytes), "r"(mbar) : "memory");
}
__device__ __forceinline__ void ldsm4(uint32_t* r, uint32_t addr) {
    asm volatile("ldmatrix.sync.aligned.m8n8.x4.shared.b16 {%0,%1,%2,%3}, [%4];"
        : "=r"(r[0]), "=r"(r[1]), "=r"(r[2]), "=r"(r[3]) : "r"(addr));
}
__device__ __forceinline__ void mma_bf16(float* d, const uint32_t* a, const uint32_t* b) {
    asm volatile(
        "mma.sync.aligned.m16n8k16.row.col.f32.bf16.bf16.f32 "
        "{%0,%1,%2,%3},{%4,%5,%6,%7},{%8,%9},{%0,%1,%2,%3};"
        : "+f"(d[0]), "+f"(d[1]), "+f"(d[2]), "+f"(d[3])
        : "r"(a[0]), "r"(a[1]), "r"(a[2]), "r"(a[3]), "r"(b[0]), "r"(b[1]));
}

// ---------------------------------------------------------------------------
__global__ void convert_labels_kernel(const int* __restrict__ raw) {
    __shared__ int nz;
    if (threadIdx.x == 0) nz = 0;
    __syncthreads();
    int local = 0;
    for (int i = threadIdx.x; i < NB / 2; i += blockDim.x)
        local |= (raw[2 * i + 1] != 0);
    if (local) atomicOr(&nz, 1);
    __syncthreads();
    const bool is64 = (nz == 0);
    for (int i = threadIdx.x; i < NB; i += blockDim.x) {
        g_lab[i]  = is64 ? raw[2 * i] : raw[i];
        g_sall[i] = 0.f;
        g_spos[i] = 0.f;
    }
}

// ---------------------------------------------------------------------------
// Normalize + split + store K-chunk-major, SW128-pre-swizzled:
//   element (r, d): kc = d/64, c = d%64 -> chunk plane kc, byte offset
//   sw128(r*128 + (c/8)*16) + (c%8)*2 within the plane.
__global__ void normalize_kernel(const float* __restrict__ emb) {
    __shared__ float ws[8];
    const int r = blockIdx.x, d = threadIdx.x;
    float v  = emb[r * ND + d];
    float ss = v * v;
    #pragma unroll
    for (int off = 16; off > 0; off >>= 1)
        ss += __shfl_xor_sync(0xffffffffu, ss, off);
    if ((d & 31) == 0) ws[d >> 5] = ss;
    __syncthreads();
    float tot = ws[0] + ws[1] + ws[2] + ws[3] + ws[4] + ws[5] + ws[6] + ws[7];
    float nrm = fmaxf(sqrtf(tot), 1e-12f);
    float e   = v / nrm;
    __nv_bfloat16 hi = __float2bfloat16(e);
    float lo = e - __bfloat162float(hi);

    const int kc = d >> 6, c = d & 63, k16 = c >> 3, b = c & 7;
    const uint32_t idx = (uint32_t)kc * CHUNK_ELEMS
                       + (sw128((uint32_t)r * 128 + (uint32_t)k16 * 16) >> 1) + b;
    g_hi[idx] = hi;
    g_lo[idx] = __float2bfloat16(lo);
}

// ---------------------------------------------------------------------------
__global__ void __launch_bounds__(NTHR, 1) gemm_lse_kernel() {
    extern __shared__ char smem[];
    const uint32_t sb = smem_u32(smem);
    int*   lab_sm  = (int*)(smem + LAB_OFF);
    float* sall_sm = (float*)(smem + SALL_OFF);
    float* spos_sm = (float*)(smem + SPOS_OFF);
    const uint32_t MB0 = sb + CTRL_OFF, MB1 = sb + CTRL_OFF + 8;

    const int tid  = threadIdx.x;
    const int wid  = tid >> 5, lane = tid & 31;
    const int wm   = wid >> 2;           // 0..1  (64 rows each)
    const int wn   = wid & 3;            // 0..3  (64 cols each)
    const int rowbase = (int)(blockIdx.x >> 5) * BM;   // 64 row tiles
    const int colbase = (int)(blockIdx.x & 31) * BN;   // 32 col tiles

    // prologue: labels + smem accumulators + mbarriers + both stages in flight
    lab_sm[tid] = g_lab[colbase + tid];
    if (tid < BM) { sall_sm[tid] = 0.f; spos_sm[tid] = 0.f; }
    if (tid == 0) { MBAR_INIT(MB0, 1); MBAR_INIT(MB1, 1); }
    __syncthreads();
    if (tid == 0) {
        #pragma unroll
        for (int kc = 0; kc < 2; ++kc) {
            const uint32_t mb = kc ? MB1 : MB0;
            const uint32_t st = sb + kc * STAGE_BYTES;
            const size_t ao = (size_t)kc * CHUNK_ELEMS + (size_t)rowbase * KC;
            const size_t bo = (size_t)kc * CHUNK_ELEMS + (size_t)colbase * KC;
            MBAR_EXPECT_TX(mb, STAGE_BYTES);
            bulk_ld(st,          g_hi + ao, 16384, mb);
            bulk_ld(st + 16384,  g_lo + ao, 16384, mb);
            bulk_ld(st + 32768,  g_hi + bo, 32768, mb);
            bulk_ld(st + 65536,  g_lo + bo, 32768, mb);
        }
    }

    // ldmatrix lane addressing constants
    const uint32_t a_row = ((lane >> 3) & 1) * 8 + (lane & 7);
    const uint32_t a_kb  = ((lane >> 4) & 1) * 16;
    const uint32_t b_row = ((lane >> 4) & 1) * 8 + (lane & 7);
    const uint32_t b_kb  = ((lane >> 3) & 1) * 16;
    const uint32_t xm    = (uint32_t)(lane & 7) << 4;
    const uint32_t arow_off = (wm * 64 + a_row) * 128;
    const uint32_t brow_off = (wn * 64 + b_row) * 128;

    float acc[4][8][4];
    #pragma unroll
    for (int mt = 0; mt < 4; ++mt)
        #pragma unroll
        for (int nt = 0; nt < 8; ++nt)
            #pragma unroll
            for (int e = 0; e < 4; ++e) acc[mt][nt][e] = 0.f;

    for (int kc = 0; kc < ND / KC; ++kc) {           // 4 chunks
        MBAR_WAIT((kc & 1) ? MB1 : MB0, (kc >> 1) & 1);

        const uint32_t st = sb + (kc & 1) * STAGE_BYTES;
        #pragma unroll
        for (int k16 = 0; k16 < 4; ++k16) {
            const uint32_t akx = ((uint32_t)(k16 * 32) + a_kb) ^ xm;
            const uint32_t bkx = ((uint32_t)(k16 * 32) + b_kb) ^ xm;
            uint32_t ah[4][4], al[4][4], bh[4][4], bl[4][4];
            #pragma unroll
            for (int mt = 0; mt < 4; ++mt) {
                ldsm4(ah[mt], st +         arow_off + mt * 2048 + akx);
                ldsm4(al[mt], st + 16384 + arow_off + mt * 2048 + akx);
            }
            #pragma unroll
            for (int p = 0; p < 4; ++p) {
                ldsm4(bh[p], st + 32768 + brow_off + p * 2048 + bkx);
                ldsm4(bl[p], st + 65536 + brow_off + p * 2048 + bkx);
            }
            #pragma unroll
            for (int mt = 0; mt < 4; ++mt)
                #pragma unroll
                for (int nt = 0; nt < 8; ++nt)
                    mma_bf16(acc[mt][nt], ah[mt], &bh[nt >> 1][(nt & 1) * 2]);
            #pragma unroll
            for (int mt = 0; mt < 4; ++mt)
                #pragma unroll
                for (int nt = 0; nt < 8; ++nt)
                    mma_bf16(acc[mt][nt], ah[mt], &bl[nt >> 1][(nt & 1) * 2]);
            #pragma unroll
            for (int mt = 0; mt < 4; ++mt)
                #pragma unroll
                for (int nt = 0; nt < 8; ++nt)
                    mma_bf16(acc[mt][nt], al[mt], &bh[nt >> 1][(nt & 1) * 2]);
        }
        __syncthreads();                             // all warps done with buffer
        if (tid == 0 && kc < 2) {                    // refill same buffer, kc+2
            const int nk = kc + 2;
            const uint32_t mb = (kc & 1) ? MB1 : MB0;
            const uint32_t dst = sb + (kc & 1) * STAGE_BYTES;
            const size_t ao = (size_t)nk * CHUNK_ELEMS + (size_t)rowbase * KC;
            const size_t bo = (size_t)nk * CHUNK_ELEMS + (size_t)colbase * KC;
            MBAR_EXPECT_TX(mb, STAGE_BYTES);
            bulk_ld(dst,          g_hi + ao, 16384, mb);
            bulk_ld(dst + 16384,  g_lo + ao, 16384, mb);
            bulk_ld(dst + 32768,  g_hi + bo, 32768, mb);
            bulk_ld(dst + 65536,  g_lo + bo, 32768, mb);
        }
    }

    // ================= fused epilogue =================
    const float INV_T = 14.285714285714286f;
    int labc[16];
    #pragma unroll
    for (int nt = 0; nt < 8; ++nt) {
        const int cl = wn * 64 + nt * 8 + 2 * (lane & 3);
        labc[2 * nt]     = lab_sm[cl];
        labc[2 * nt + 1] = lab_sm[cl + 1];
    }
    int rlab[8];
    #pragma unroll
    for (int mt = 0; mt < 4; ++mt) {
        const int r0 = rowbase + wm * 64 + mt * 16 + (lane >> 2);
        rlab[2 * mt]     = g_lab[r0];
        rlab[2 * mt + 1] = g_lab[r0 + 8];
    }

    float psall[8], pspos[8];
    #pragma unroll
    for (int r = 0; r < 8; ++r) { psall[r] = 0.f; pspos[r] = 0.f; }

    #pragma unroll
    for (int mt = 0; mt < 4; ++mt) {
        const int rg0 = rowbase + wm * 64 + mt * 16 + (lane >> 2);
        const int rg1 = rg0 + 8;
        #pragma unroll
        for (int nt = 0; nt < 8; ++nt) {
            const int cg0 = colbase + wn * 64 + nt * 8 + 2 * (lane & 3);
            const int cg1 = cg0 + 1;
            const float* a4 = acc[mt][nt];
            float v0 = __expf(fmaf(a4[0], INV_T, -INV_T));
            float v1 = __expf(fmaf(a4[1], INV_T, -INV_T));
            float v2 = __expf(fmaf(a4[2], INV_T, -INV_T));
            float v3 = __expf(fmaf(a4[3], INV_T, -INV_T));
            if (rg0 == cg0) v0 = 0.f;
            if (rg0 == cg1) v1 = 0.f;
            if (rg1 == cg0) v2 = 0.f;
            if (rg1 == cg1) v3 = 0.f;
            psall[2 * mt]     += v0 + v1;
            psall[2 * mt + 1] += v2 + v3;
            if (labc[2 * nt]     == rlab[2 * mt])     pspos[2 * mt]     += v0;
            if (labc[2 * nt + 1] == rlab[2 * mt])     pspos[2 * mt]     += v1;
            if (labc[2 * nt]     == rlab[2 * mt + 1]) pspos[2 * mt + 1] += v2;
            if (labc[2 * nt + 1] == rlab[2 * mt + 1]) pspos[2 * mt + 1] += v3;
        }
    }
    #pragma unroll
    for (int mt = 0; mt < 4; ++mt) {
        const int rl0 = wm * 64 + mt * 16 + (lane >> 2);
        atomicAdd(&sall_sm[rl0],     psall[2 * mt]);
        atomicAdd(&sall_sm[rl0 + 8], psall[2 * mt + 1]);
        atomicAdd(&spos_sm[rl0],     pspos[2 * mt]);
        atomicAdd(&spos_sm[rl0 + 8], pspos[2 * mt + 1]);
    }
    __syncthreads();
    if (tid < BM) {
        atomicAdd(&g_sall[rowbase + tid], sall_sm[tid]);
        atomicAdd(&g_spos[rowbase + tid], spos_sm[tid]);
    }
}

// ---------------------------------------------------------------------------
__global__ void finalize_kernel(float* __restrict__ out) {
    __shared__ float ssum[32];
    __shared__ int   scnt[32];
    const int tid = threadIdx.x, w = tid >> 5, l = tid & 31;
    float ls = 0.f; int lc = 0;
    for (int r = tid; r < NB; r += 1024) {
        float sp = g_spos[r];
        if (sp > 0.f) { ls += __logf(g_sall[r] / sp); lc++; }
    }
    #pragma unroll
    for (int off = 16; off > 0; off >>= 1) {
        ls += __shfl_xor_sync(0xffffffffu, ls, off);
        lc += __shfl_xor_sync(0xffffffffu, lc, off);
    }
    if (l == 0) { ssum[w] = ls; scnt[w] = lc; }
    __syncthreads();
    if (w == 0) {
        ls = ssum[l]; lc = scnt[l];
        #pragma unroll
        for (int off = 16; off > 0; off >>= 1) {
            ls += __shfl_xor_sync(0xffffffffu, ls, off);
            lc += __shfl_xor_sync(0xffffffffu, lc, off);
        }
        if (l == 0) out[0] = (lc > 0) ? (ls / (float)lc) : 0.0f;
    }
}

// ---------------------------------------------------------------------------
extern "C" void kernel_launch(void* const* d_in, const int* in_sizes, int n_in,
                              void* d_out, int out_size) {
    const float* emb = (const float*)d_in[0];
    const int*   lab = (const int*)d_in[1];
    float*       out = (float*)d_out;

    cudaFuncSetAttribute(gemm_lse_kernel,
                         cudaFuncAttributeMaxDynamicSharedMemorySize, SMEM_TOTAL);

    convert_labels_kernel<<<1, 1024>>>(lab);
    normalize_kernel<<<NB, ND>>>(emb);
    gemm_lse_kernel<<<(NB / BM) * (NB / BN), NTHR, SMEM_TOTAL>>>();
    finalize_kernel<<<1, 1024>>>(out);
}

// round 12
// speedup vs baseline: 4.3759x; 1.8686x over previous
#include <cuda_runtime.h>
#include <cuda_fp16.h>
#include <cstdint>

// ---------------------------------------------------------------------------
// InfoNCE supervised-contrastive loss — single-product fp16 HMMA, full-K
// smem residency (all 4 K-chunks prefetched via cp.async.bulk).
//   k1: label width detect (i64/i32) -> i32; zero row accumulators
//   k2: normalize rows (fp32), store fp16, K-chunk-major, PRE-SWIZZLED (SW128)
//       so linear bulk copies land MMA-ready in smem.
//   k3: 2048 CTAs, 128x256 tile; 8 bulk copies prefetch A(64KB)+B(128KB);
//       mma.sync.m16n8k16.f16 -> fp32 acc; fused exp epilogue, per-row sums.
//   k4: per-row __logf(s_all/s_pos), mean over rows with positives.
// ---------------------------------------------------------------------------

#define NB    8192
#define ND    256
#define BM    128
#define BN    256
#define KC    64
#define NTHR  256
#define CHUNK_ELEMS (NB * KC)          // elements per K-chunk plane

__device__ __align__(1024) __half g_e[NB * ND];   // [4][8192][64] swizzled fp16
__device__ int   g_lab[NB];
__device__ float g_sall[NB];
__device__ float g_spos[NB];

// ---- smem layout (bytes) ----------------------------------------------------
// stage kc (kc=0..3) at kc*49152:
//   A [128][64]fp16 swizzled : +0      (16 KB)
//   B [256][64]fp16 swizzled : +16384  (32 KB)
#define STAGE_BYTES 49152
#define LAB_OFF     196608     // 256 ints
#define SALL_OFF    197632     // 128 floats
#define SPOS_OFF    198144     // 128 floats
#define CTRL_OFF    198656     // 4 mbarriers
#define SMEM_TOTAL  198784

// ---- PTX helpers ------------------------------------------------------------
__device__ __forceinline__ uint32_t smem_u32(const void* p) {
    uint32_t a;
    asm("{ .reg .u64 t; cvta.to.shared.u64 t, %1; cvt.u32.u64 %0, t; }" : "=r"(a) : "l"(p));
    return a;
}
__device__ __forceinline__ uint32_t sw128(uint32_t off) {
    return off ^ ((off >> 3) & 0x70);   // permutes 16B granules within a 128B row
}
#define MBAR_INIT(addr, cnt) \
    asm volatile("mbarrier.init.shared.b64 [%0], %1;" :: "r"(addr), "r"((uint32_t)(cnt)) : "memory")
#define MBAR_EXPECT_TX(addr, bytes) \
    asm volatile("mbarrier.arrive.expect_tx.shared.b64 _, [%0], %1;" :: "r"(addr), "r"((uint32_t)(bytes)) : "memory")
#define MBAR_WAIT(addr, parity) do {                                                   \
    asm volatile("{\n\t.reg .pred P1;\n\t"                                             \
        "WAIT_LP_%=:\n\t"                                                              \
        "mbarrier.try_wait.parity.acquire.cta.shared::cta.b64 P1, [%0], %1, 0x989680;\n\t" \
        "@P1 bra.uni WAIT_DN_%=;\n\t"                                                  \
        "bra.uni WAIT_LP_%=;\n\t"                                                      \
        "WAIT_DN_%=:\n\t}"                                                             \
        :: "r"(addr), "r"((uint32_t)(parity)) : "memory");                             \
} while (0)
__device__ __forceinline__ void bulk_ld(uint32_t dst, const void* src,
                                        uint32_t bytes, uint32_t mbar) {
    asm volatile(
        "cp.async.bulk.shared::cta.global.mbarrier::complete_tx::bytes [%0], [%1], %2, [%3];"
        :: "r"(dst), "l"(src), "r"(bytes), "r"(mbar) : "memory");
}
__device__ __forceinline__ void ldsm4(uint32_t* r, uint32_t addr) {
    asm volatile("ldmatrix.sync.aligned.m8n8.x4.shared.b16 {%0,%1,%2,%3}, [%4];"
        : "=r"(r[0]), "=r"(r[1]), "=r"(r[2]), "=r"(r[3]) : "r"(addr));
}
__device__ __forceinline__ void mma_f16(float* d, const uint32_t* a, const uint32_t* b) {
    asm volatile(
        "mma.sync.aligned.m16n8k16.row.col.f32.f16.f16.f32 "
        "{%0,%1,%2,%3},{%4,%5,%6,%7},{%8,%9},{%0,%1,%2,%3};"
        : "+f"(d[0]), "+f"(d[1]), "+f"(d[2]), "+f"(d[3])
        : "r"(a[0]), "r"(a[1]), "r"(a[2]), "r"(a[3]), "r"(b[0]), "r"(b[1]));
}

// ---------------------------------------------------------------------------
__global__ void convert_labels_kernel(const int* __restrict__ raw) {
    __shared__ int nz;
    if (threadIdx.x == 0) nz = 0;
    __syncthreads();
    int local = 0;
    for (int i = threadIdx.x; i < NB / 2; i += blockDim.x)
        local |= (raw[2 * i + 1] != 0);
    if (local) atomicOr(&nz, 1);
    __syncthreads();
    const bool is64 = (nz == 0);
    for (int i = threadIdx.x; i < NB; i += blockDim.x) {
        g_lab[i]  = is64 ? raw[2 * i] : raw[i];
        g_sall[i] = 0.f;
        g_spos[i] = 0.f;
    }
}

// ---------------------------------------------------------------------------
// Normalize (fp32) + store fp16, K-chunk-major, SW128-pre-swizzled:
//   element (r, d): kc = d/64, c = d%64 -> plane kc, halfword index
//   (sw128(r*128 + (c/8)*16) >> 1) + (c%8).
__global__ void normalize_kernel(const float* __restrict__ emb) {
    __shared__ float ws[8];
    const int r = blockIdx.x, d = threadIdx.x;
    float v  = emb[r * ND + d];
    float ss = v * v;
    #pragma unroll
    for (int off = 16; off > 0; off >>= 1)
        ss += __shfl_xor_sync(0xffffffffu, ss, off);
    if ((d & 31) == 0) ws[d >> 5] = ss;
    __syncthreads();
    float tot = ws[0] + ws[1] + ws[2] + ws[3] + ws[4] + ws[5] + ws[6] + ws[7];
    float nrm = fmaxf(sqrtf(tot), 1e-12f);
    float e   = v / nrm;

    const int kc = d >> 6, c = d & 63, k16 = c >> 3, b = c & 7;
    const uint32_t idx = (uint32_t)kc * CHUNK_ELEMS
                       + (sw128((uint32_t)r * 128 + (uint32_t)k16 * 16) >> 1) + b;
    g_e[idx] = __float2half(e);
}

// ---------------------------------------------------------------------------
__global__ void __launch_bounds__(NTHR, 1) gemm_lse_kernel() {
    extern __shared__ char smem[];
    const uint32_t sb = smem_u32(smem);
    int*   lab_sm  = (int*)(smem + LAB_OFF);
    float* sall_sm = (float*)(smem + SALL_OFF);
    float* spos_sm = (float*)(smem + SPOS_OFF);

    const int tid  = threadIdx.x;
    const int wid  = tid >> 5, lane = tid & 31;
    const int wm   = wid >> 2;           // 0..1  (64 rows each)
    const int wn   = wid & 3;            // 0..3  (64 cols each)
    const int rowbase = (int)(blockIdx.x >> 5) * BM;   // 64 row tiles
    const int colbase = (int)(blockIdx.x & 31) * BN;   // 32 col tiles

    // prologue: labels + smem accumulators + 4 mbarriers
    lab_sm[tid] = g_lab[colbase + tid];
    if (tid < BM) { sall_sm[tid] = 0.f; spos_sm[tid] = 0.f; }
    if (tid == 0) {
        #pragma unroll
        for (int kc = 0; kc < 4; ++kc) MBAR_INIT(sb + CTRL_OFF + 8 * kc, 1);
    }
    __syncthreads();
    // prefetch ALL FOUR K-chunks (192 KB) — no mid-loop refills needed
    if (tid == 0) {
        #pragma unroll
        for (int kc = 0; kc < 4; ++kc) {
            const uint32_t mb = sb + CTRL_OFF + 8 * kc;
            const uint32_t st = sb + kc * STAGE_BYTES;
            const size_t ao = (size_t)kc * CHUNK_ELEMS + (size_t)rowbase * KC;
            const size_t bo = (size_t)kc * CHUNK_ELEMS + (size_t)colbase * KC;
            MBAR_EXPECT_TX(mb, STAGE_BYTES);
            bulk_ld(st,          g_e + ao, 16384, mb);
            bulk_ld(st + 16384,  g_e + bo, 32768, mb);
        }
    }

    // ldmatrix lane addressing constants
    const uint32_t a_row = ((lane >> 3) & 1) * 8 + (lane & 7);
    const uint32_t a_kb  = ((lane >> 4) & 1) * 16;
    const uint32_t b_row = ((lane >> 4) & 1) * 8 + (lane & 7);
    const uint32_t b_kb  = ((lane >> 3) & 1) * 16;
    const uint32_t xm    = (uint32_t)(lane & 7) << 4;
    const uint32_t arow_off = (wm * 64 + a_row) * 128;
    const uint32_t brow_off = (wn * 64 + b_row) * 128;

    float acc[4][8][4];
    #pragma unroll
    for (int mt = 0; mt < 4; ++mt)
        #pragma unroll
        for (int nt = 0; nt < 8; ++nt)
            #pragma unroll
            for (int e = 0; e < 4; ++e) acc[mt][nt][e] = 0.f;

    #pragma unroll
    for (int kc = 0; kc < ND / KC; ++kc) {           // 4 chunks
        MBAR_WAIT(sb + CTRL_OFF + 8 * kc, 0);
        const uint32_t st = sb + kc * STAGE_BYTES;
        #pragma unroll
        for (int k16 = 0; k16 < 4; ++k16) {
            const uint32_t akx = ((uint32_t)(k16 * 32) + a_kb) ^ xm;
            const uint32_t bkx = ((uint32_t)(k16 * 32) + b_kb) ^ xm;
            uint32_t ah[4][4], bh[4][4];
            #pragma unroll
            for (int mt = 0; mt < 4; ++mt)
                ldsm4(ah[mt], st + arow_off + mt * 2048 + akx);
            #pragma unroll
            for (int p = 0; p < 4; ++p)
                ldsm4(bh[p], st + 16384 + brow_off + p * 2048 + bkx);
            #pragma unroll
            for (int mt = 0; mt < 4; ++mt)
                #pragma unroll
                for (int nt = 0; nt < 8; ++nt)
                    mma_f16(acc[mt][nt], ah[mt], &bh[nt >> 1][(nt & 1) * 2]);
        }
    }

    // ================= fused epilogue =================
    const float INV_T = 14.285714285714286f;
    int labc[16];
    #pragma unroll
    for (int nt = 0; nt < 8; ++nt) {
        const int cl = wn * 64 + nt * 8 + 2 * (lane & 3);
        labc[2 * nt]     = lab_sm[cl];
        labc[2 * nt + 1] = lab_sm[cl + 1];
    }
    int rlab[8];
    #pragma unroll
    for (int mt = 0; mt < 4; ++mt) {
        const int r0 = rowbase + wm * 64 + mt * 16 + (lane >> 2);
        rlab[2 * mt]     = g_lab[r0];
        rlab[2 * mt + 1] = g_lab[r0 + 8];
    }

    float psall[8], pspos[8];
    #pragma unroll
    for (int r = 0; r < 8; ++r) { psall[r] = 0.f; pspos[r] = 0.f; }

    #pragma unroll
    for (int mt = 0; mt < 4; ++mt) {
        const int rg0 = rowbase + wm * 64 + mt * 16 + (lane >> 2);
        const int rg1 = rg0 + 8;
        #pragma unroll
        for (int nt = 0; nt < 8; ++nt) {
            const int cg0 = colbase + wn * 64 + nt * 8 + 2 * (lane & 3);
            const int cg1 = cg0 + 1;
            const float* a4 = acc[mt][nt];
            float v0 = __expf(fmaf(a4[0], INV_T, -INV_T));
            float v1 = __expf(fmaf(a4[1], INV_T, -INV_T));
            float v2 = __expf(fmaf(a4[2], INV_T, -INV_T));
            float v3 = __expf(fmaf(a4[3], INV_T, -INV_T));
            if (rg0 == cg0) v0 = 0.f;
            if (rg0 == cg1) v1 = 0.f;
            if (rg1 == cg0) v2 = 0.f;
            if (rg1 == cg1) v3 = 0.f;
            psall[2 * mt]     += v0 + v1;
            psall[2 * mt + 1] += v2 + v3;
            if (labc[2 * nt]     == rlab[2 * mt])     pspos[2 * mt]     += v0;
            if (labc[2 * nt + 1] == rlab[2 * mt])     pspos[2 * mt]     += v1;
            if (labc[2 * nt]     == rlab[2 * mt + 1]) pspos[2 * mt + 1] += v2;
            if (labc[2 * nt + 1] == rlab[2 * mt + 1]) pspos[2 * mt + 1] += v3;
        }
    }
    #pragma unroll
    for (int mt = 0; mt < 4; ++mt) {
        const int rl0 = wm * 64 + mt * 16 + (lane >> 2);
        atomicAdd(&sall_sm[rl0],     psall[2 * mt]);
        atomicAdd(&sall_sm[rl0 + 8], psall[2 * mt + 1]);
        atomicAdd(&spos_sm[rl0],     pspos[2 * mt]);
        atomicAdd(&spos_sm[rl0 + 8], pspos[2 * mt + 1]);
    }
    __syncthreads();
    if (tid < BM) {
        atomicAdd(&g_sall[rowbase + tid], sall_sm[tid]);
        atomicAdd(&g_spos[rowbase + tid], spos_sm[tid]);
    }
}

// ---------------------------------------------------------------------------
__global__ void finalize_kernel(float* __restrict__ out) {
    __shared__ float ssum[32];
    __shared__ int   scnt[32];
    const int tid = threadIdx.x, w = tid >> 5, l = tid & 31;
    // batch the 8 row-loads per thread for MLP (was latency-bound)
    float sp[8], sa[8];
    #pragma unroll
    for (int i = 0; i < 8; ++i) {
        sp[i] = g_spos[tid + 1024 * i];
        sa[i] = g_sall[tid + 1024 * i];
    }
    float ls = 0.f; int lc = 0;
    #pragma unroll
    for (int i = 0; i < 8; ++i) {
        if (sp[i] > 0.f) { ls += __logf(sa[i] / sp[i]); lc++; }
    }
    #pragma unroll
    for (int off = 16; off > 0; off >>= 1) {
        ls += __shfl_xor_sync(0xffffffffu, ls, off);
        lc += __shfl_xor_sync(0xffffffffu, lc, off);
    }
    if (l == 0) { ssum[w] = ls; scnt[w] = lc; }
    __syncthreads();
    if (w == 0) {
        ls = ssum[l]; lc = scnt[l];
        #pragma unroll
        for (int off = 16; off > 0; off >>= 1) {
            ls += __shfl_xor_sync(0xffffffffu, ls, off);
            lc += __shfl_xor_sync(0xffffffffu, lc, off);
        }
        if (l == 0) out[0] = (lc > 0) ? (ls / (float)lc) : 0.0f;
    }
}

// ---------------------------------------------------------------------------
extern "C" void kernel_launch(void* const* d_in, const int* in_sizes, int n_in,
                              void* d_out, int out_size) {
    const float* emb = (const float*)d_in[0];
    const int*   lab = (const int*)d_in[1];
    float*       out = (float*)d_out;

    cudaFuncSetAttribute(gemm_lse_kernel,
                         cudaFuncAttributeMaxDynamicSharedMemorySize, SMEM_TOTAL);

    convert_labels_kernel<<<1, 1024>>>(lab);
    normalize_kernel<<<NB, ND>>>(emb);
    gemm_lse_kernel<<<(NB / BM) * (NB / BN), NTHR, SMEM_TOTAL>>>();
    finalize_kernel<<<1, 1024>>>(out);
}

// round 13
// speedup vs baseline: 5.6452x; 1.2901x over previous
#include <cuda_runtime.h>
#include <cuda_fp16.h>
#include <cstdint>

// ---------------------------------------------------------------------------
// InfoNCE supervised-contrastive loss — fp16 HMMA, multi-tile CTAs with
// cross-tile cp.async.bulk pipeline (tile-1 loads overlap tile-0 epilogue).
//   k1: label width detect (i64/i32) -> i32; zero row accumulators
//   k2: normalize rows (fp32), store fp16, K-chunk-major, PRE-SWIZZLED (SW128)
//   k3: 1024 CTAs = 64 row-strips x 16 col-groups; 2 tiles of 128x256 per CTA,
//       shared A panel; B ring of 4x32KB buffers refilled across tiles;
//       mma.sync.m16n8k16.f16 -> fp32; fused ex2 epilogue, per-row sums kept
//       in registers across tiles.
//   k4: per-row __logf(s_all/s_pos), mean over rows with positives.
// ---------------------------------------------------------------------------

#define NB    8192
#define ND    256
#define BM    128
#define BN    256
#define KC    64
#define NCT   2                        // tiles per CTA
#define NTHR  256
#define CHUNK_ELEMS (NB * KC)          // elements per K-chunk plane

__device__ __align__(1024) __half g_e[NB * ND];   // [4][8192][64] swizzled fp16
__device__ int   g_lab[NB];
__device__ float g_sall[NB];
__device__ float g_spos[NB];

// ---- smem layout (bytes) ----------------------------------------------------
#define A_OFF      0           // 4 chunks x [128][64] fp16 swizzled = 64 KB
#define B_OFF      65536       // 4 bufs x [256][64] fp16 swizzled = 128 KB
#define LAB_OFF    196608      // 512 ints (2 tiles)
#define SALL_OFF   198656      // 128 floats
#define SPOS_OFF   199168      // 128 floats
#define CTRL_OFF   199680      // 4 mbarriers
#define SMEM_TOTAL 199808

// ---- PTX helpers ------------------------------------------------------------
__device__ __forceinline__ uint32_t smem_u32(const void* p) {
    uint32_t a;
    asm("{ .reg .u64 t; cvta.to.shared.u64 t, %1; cvt.u32.u64 %0, t; }" : "=r"(a) : "l"(p));
    return a;
}
__device__ __forceinline__ uint32_t sw128(uint32_t off) {
    return off ^ ((off >> 3) & 0x70);   // permutes 16B granules within a 128B row
}
__device__ __forceinline__ float ex2(float x) {
    float y;
    asm("ex2.approx.ftz.f32 %0, %1;" : "=f"(y) : "f"(x));
    return y;
}
#define MBAR_INIT(addr, cnt) \
    asm volatile("mbarrier.init.shared.b64 [%0], %1;" :: "r"(addr), "r"((uint32_t)(cnt)) : "memory")
#define MBAR_EXPECT_TX(addr, bytes) \
    asm volatile("mbarrier.arrive.expect_tx.shared.b64 _, [%0], %1;" :: "r"(addr), "r"((uint32_t)(bytes)) : "memory")
#define MBAR_WAIT(addr, parity) do {                                                   \
    asm volatile("{\n\t.reg .pred P1;\n\t"                                             \
        "WAIT_LP_%=:\n\t"                                                              \
        "mbarrier.try_wait.parity.acquire.cta.shared::cta.b64 P1, [%0], %1, 0x989680;\n\t" \
        "@P1 bra.uni WAIT_DN_%=;\n\t"                                                  \
        "bra.uni WAIT_LP_%=;\n\t"                                                      \
        "WAIT_DN_%=:\n\t}"                                                             \
        :: "r"(addr), "r"((uint32_t)(parity)) : "memory");                             \
} while (0)
__device__ __forceinline__ void bulk_ld(uint32_t dst, const void* src,
                                        uint32_t bytes, uint32_t mbar) {
    asm volatile(
        "cp.async.bulk.shared::cta.global.mbarrier::complete_tx::bytes [%0], [%1], %2, [%3];"
        :: "r"(dst), "l"(src), "r"(bytes), "r"(mbar) : "memory");
}
__device__ __forceinline__ void ldsm4(uint32_t* r, uint32_t addr) {
    asm volatile("ldmatrix.sync.aligned.m8n8.x4.shared.b16 {%0,%1,%2,%3}, [%4];"
        : "=r"(r[0]), "=r"(r[1]), "=r"(r[2]), "=r"(r[3]) : "r"(addr));
}
__device__ __forceinline__ void mma_f16(float* d, const uint32_t* a, const uint32_t* b) {
    asm volatile(
        "mma.sync.aligned.m16n8k16.row.col.f32.f16.f16.f32 "
        "{%0,%1,%2,%3},{%4,%5,%6,%7},{%8,%9},{%0,%1,%2,%3};"
        : "+f"(d[0]), "+f"(d[1]), "+f"(d[2]), "+f"(d[3])
        : "r"(a[0]), "r"(a[1]), "r"(a[2]), "r"(a[3]), "r"(b[0]), "r"(b[1]));
}

// ---------------------------------------------------------------------------
__global__ void convert_labels_kernel(const int* __restrict__ raw) {
    __shared__ int nz;
    if (threadIdx.x == 0) nz = 0;
    __syncthreads();
    int local = 0;
    for (int i = threadIdx.x; i < NB / 2; i += blockDim.x)
        local |= (raw[2 * i + 1] != 0);
    if (local) atomicOr(&nz, 1);
    __syncthreads();
    const bool is64 = (nz == 0);
    for (int i = threadIdx.x; i < NB; i += blockDim.x) {
        g_lab[i]  = is64 ? raw[2 * i] : raw[i];
        g_sall[i] = 0.f;
        g_spos[i] = 0.f;
    }
}

// ---------------------------------------------------------------------------
__global__ void normalize_kernel(const float* __restrict__ emb) {
    __shared__ float ws[8];
    const int r = blockIdx.x, d = threadIdx.x;
    float v  = emb[r * ND + d];
    float ss = v * v;
    #pragma unroll
    for (int off = 16; off > 0; off >>= 1)
        ss += __shfl_xor_sync(0xffffffffu, ss, off);
    if ((d & 31) == 0) ws[d >> 5] = ss;
    __syncthreads();
    float tot = ws[0] + ws[1] + ws[2] + ws[3] + ws[4] + ws[5] + ws[6] + ws[7];
    float nrm = fmaxf(sqrtf(tot), 1e-12f);
    float e   = v / nrm;

    const int kc = d >> 6, c = d & 63, k16 = c >> 3, b = c & 7;
    const uint32_t idx = (uint32_t)kc * CHUNK_ELEMS
                       + (sw128((uint32_t)r * 128 + (uint32_t)k16 * 16) >> 1) + b;
    g_e[idx] = __float2half(e);
}

// ---------------------------------------------------------------------------
__global__ void __launch_bounds__(NTHR, 1) gemm_lse_kernel() {
    extern __shared__ char smem[];
    const uint32_t sb = smem_u32(smem);
    int*   lab_sm  = (int*)(smem + LAB_OFF);
    float* sall_sm = (float*)(smem + SALL_OFF);
    float* spos_sm = (float*)(smem + SPOS_OFF);

    const int tid  = threadIdx.x;
    const int wid  = tid >> 5, lane = tid & 31;
    const int wm   = wid >> 2;           // 0..1  (64 rows each)
    const int wn   = wid & 3;            // 0..3  (64 cols each)
    const int rowbase = (int)(blockIdx.x >> 4) * BM;        // 64 strips
    const int cgbase  = (int)(blockIdx.x & 15) * (BN * NCT); // 16 col groups

    // prologue: labels (both tiles) + smem row accumulators + mbarriers
    lab_sm[tid]       = g_lab[cgbase + tid];
    lab_sm[tid + 256] = g_lab[cgbase + 256 + tid];
    if (tid < BM) { sall_sm[tid] = 0.f; spos_sm[tid] = 0.f; }
    if (tid == 0) {
        #pragma unroll
        for (int kc = 0; kc < 4; ++kc) MBAR_INIT(sb + CTRL_OFF + 8 * kc, 1);
    }
    __syncthreads();
    // prefetch A chunk kc + B(tile0, kc) into buffer kc
    if (tid == 0) {
        #pragma unroll
        for (int kc = 0; kc < 4; ++kc) {
            const uint32_t mb = sb + CTRL_OFF + 8 * kc;
            const size_t ao = (size_t)kc * CHUNK_ELEMS + (size_t)rowbase * KC;
            const size_t bo = (size_t)kc * CHUNK_ELEMS + (size_t)cgbase * KC;
            MBAR_EXPECT_TX(mb, 16384 + 32768);
            bulk_ld(sb + A_OFF + kc * 16384, g_e + ao, 16384, mb);
            bulk_ld(sb + B_OFF + kc * 32768, g_e + bo, 32768, mb);
        }
    }

    // ldmatrix lane addressing constants
    const uint32_t a_row = ((lane >> 3) & 1) * 8 + (lane & 7);
    const uint32_t a_kb  = ((lane >> 4) & 1) * 16;
    const uint32_t b_row = ((lane >> 4) & 1) * 8 + (lane & 7);
    const uint32_t b_kb  = ((lane >> 3) & 1) * 16;
    const uint32_t xm    = (uint32_t)(lane & 7) << 4;
    const uint32_t arow_off = (wm * 64 + a_row) * 128;
    const uint32_t brow_off = (wn * 64 + b_row) * 128;

    // row labels (fixed across tiles)
    int rlab[8];
    #pragma unroll
    for (int mt = 0; mt < 4; ++mt) {
        const int r0 = rowbase + wm * 64 + mt * 16 + (lane >> 2);
        rlab[2 * mt]     = g_lab[r0];
        rlab[2 * mt + 1] = g_lab[r0 + 8];
    }

    // per-row partial sums persist across both tiles
    float psall[8], pspos[8];
    #pragma unroll
    for (int r = 0; r < 8; ++r) { psall[r] = 0.f; pspos[r] = 0.f; }

    const float C2 = 20.609929230246954f;   // log2(e)/T

    #pragma unroll
    for (int t = 0; t < NCT; ++t) {
        const int colbase = cgbase + t * BN;

        float acc[4][8][4];
        #pragma unroll
        for (int mt = 0; mt < 4; ++mt)
            #pragma unroll
            for (int nt = 0; nt < 8; ++nt)
                #pragma unroll
                for (int e = 0; e < 4; ++e) acc[mt][nt][e] = 0.f;

        #pragma unroll
        for (int kc = 0; kc < ND / KC; ++kc) {       // 4 chunks
            MBAR_WAIT(sb + CTRL_OFF + 8 * kc, t & 1);
            const uint32_t sa = sb + A_OFF + kc * 16384;
            const uint32_t sbuf = sb + B_OFF + kc * 32768;
            #pragma unroll
            for (int k16 = 0; k16 < 4; ++k16) {
                const uint32_t akx = ((uint32_t)(k16 * 32) + a_kb) ^ xm;
                const uint32_t bkx = ((uint32_t)(k16 * 32) + b_kb) ^ xm;
                uint32_t ah[4][4], bh[4][4];
                #pragma unroll
                for (int mt = 0; mt < 4; ++mt)
                    ldsm4(ah[mt], sa + arow_off + mt * 2048 + akx);
                #pragma unroll
                for (int p = 0; p < 4; ++p)
                    ldsm4(bh[p], sbuf + brow_off + p * 2048 + bkx);
                #pragma unroll
                for (int mt = 0; mt < 4; ++mt)
                    #pragma unroll
                    for (int nt = 0; nt < 8; ++nt)
                        mma_f16(acc[mt][nt], ah[mt], &bh[nt >> 1][(nt & 1) * 2]);
            }
            if (t < NCT - 1) {
                __syncthreads();                     // all warps done with buf kc
                if (tid == 0) {                      // refill with next tile's B
                    const uint32_t mb = sb + CTRL_OFF + 8 * kc;
                    const size_t bo = (size_t)kc * CHUNK_ELEMS
                                    + (size_t)(colbase + BN) * KC;
                    MBAR_EXPECT_TX(mb, 32768);
                    bulk_ld(sb + B_OFF + kc * 32768, g_e + bo, 32768, mb);
                }
            }
        }

        // ---- fused epilogue for tile t (overlaps tile t+1's DMA) ----
        int labc[16];
        #pragma unroll
        for (int nt = 0; nt < 8; ++nt) {
            const int cl = t * 256 + wn * 64 + nt * 8 + 2 * (lane & 3);
            labc[2 * nt]     = lab_sm[cl];
            labc[2 * nt + 1] = lab_sm[cl + 1];
        }
        const bool has_diag = (rowbase >> 8) == (colbase >> 8);

        #pragma unroll
        for (int mt = 0; mt < 4; ++mt) {
            const int rg0 = rowbase + wm * 64 + mt * 16 + (lane >> 2);
            const int rg1 = rg0 + 8;
            #pragma unroll
            for (int nt = 0; nt < 8; ++nt) {
                const float* a4 = acc[mt][nt];
                float v0 = ex2(fmaf(a4[0], C2, -C2));
                float v1 = ex2(fmaf(a4[1], C2, -C2));
                float v2 = ex2(fmaf(a4[2], C2, -C2));
                float v3 = ex2(fmaf(a4[3], C2, -C2));
                if (has_diag) {
                    const int cg0 = colbase + wn * 64 + nt * 8 + 2 * (lane & 3);
                    const int cg1 = cg0 + 1;
                    if (rg0 == cg0) v0 = 0.f;
                    if (rg0 == cg1) v1 = 0.f;
                    if (rg1 == cg0) v2 = 0.f;
                    if (rg1 == cg1) v3 = 0.f;
                }
                psall[2 * mt]     += v0 + v1;
                psall[2 * mt + 1] += v2 + v3;
                if (labc[2 * nt]     == rlab[2 * mt])     pspos[2 * mt]     += v0;
                if (labc[2 * nt + 1] == rlab[2 * mt])     pspos[2 * mt]     += v1;
                if (labc[2 * nt]     == rlab[2 * mt + 1]) pspos[2 * mt + 1] += v2;
                if (labc[2 * nt + 1] == rlab[2 * mt + 1]) pspos[2 * mt + 1] += v3;
            }
        }
    }

    // ---- flush per-row sums: smem once, then global once ----
    #pragma unroll
    for (int mt = 0; mt < 4; ++mt) {
        const int rl0 = wm * 64 + mt * 16 + (lane >> 2);
        atomicAdd(&sall_sm[rl0],     psall[2 * mt]);
        atomicAdd(&sall_sm[rl0 + 8], psall[2 * mt + 1]);
        atomicAdd(&spos_sm[rl0],     pspos[2 * mt]);
        atomicAdd(&spos_sm[rl0 + 8], pspos[2 * mt + 1]);
    }
    __syncthreads();
    if (tid < BM) {
        atomicAdd(&g_sall[rowbase + tid], sall_sm[tid]);
        atomicAdd(&g_spos[rowbase + tid], spos_sm[tid]);
    }
}

// ---------------------------------------------------------------------------
__global__ void finalize_kernel(float* __restrict__ out) {
    __shared__ float ssum[32];
    __shared__ int   scnt[32];
    const int tid = threadIdx.x, w = tid >> 5, l = tid & 31;
    float sp[8], sa[8];
    #pragma unroll
    for (int i = 0; i < 8; ++i) {
        sp[i] = g_spos[tid + 1024 * i];
        sa[i] = g_sall[tid + 1024 * i];
    }
    float ls = 0.f; int lc = 0;
    #pragma unroll
    for (int i = 0; i < 8; ++i) {
        if (sp[i] > 0.f) { ls += __logf(sa[i] / sp[i]); lc++; }
    }
    #pragma unroll
    for (int off = 16; off > 0; off >>= 1) {
        ls += __shfl_xor_sync(0xffffffffu, ls, off);
        lc += __shfl_xor_sync(0xffffffffu, lc, off);
    }
    if (l == 0) { ssum[w] = ls; scnt[w] = lc; }
    __syncthreads();
    if (w == 0) {
        ls = ssum[l]; lc = scnt[l];
        #pragma unroll
        for (int off = 16; off > 0; off >>= 1) {
            ls += __shfl_xor_sync(0xffffffffu, ls, off);
            lc += __shfl_xor_sync(0xffffffffu, lc, off);
        }
        if (l == 0) out[0] = (lc > 0) ? (ls / (float)lc) : 0.0f;
    }
}

// ---------------------------------------------------------------------------
extern "C" void kernel_launch(void* const* d_in, const int* in_sizes, int n_in,
                              void* d_out, int out_size) {
    const float* emb = (const float*)d_in[0];
    const int*   lab = (const int*)d_in[1];
    float*       out = (float*)d_out;

    cudaFuncSetAttribute(gemm_lse_kernel,
                         cudaFuncAttributeMaxDynamicSharedMemorySize, SMEM_TOTAL);

    convert_labels_kernel<<<1, 1024>>>(lab);
    normalize_kernel<<<NB, ND>>>(emb);
    gemm_lse_kernel<<<(NB / BM) * (NB / (BN * NCT)), NTHR, SMEM_TOTAL>>>();
    finalize_kernel<<<1, 1024>>>(out);
}

// round 14
// speedup vs baseline: 6.1569x; 1.0907x over previous
#include <cuda_runtime.h>
#include <cuda_fp16.h>
#include <cstdint>

// ---------------------------------------------------------------------------
// InfoNCE supervised-contrastive loss — fp16 HMMA, 512-thread CTAs
// (4 warps/SMSP to hide ldmatrix/HMMA latency), multi-tile cross-tile
// cp.async.bulk pipeline.
//   k1: label width detect (i64/i32) -> i32; zero row accumulators
//   k2: normalize rows (fp32), store fp16, K-chunk-major, PRE-SWIZZLED (SW128)
//   k3: 1024 CTAs = 64 row-strips x 16 col-groups; 2 tiles of 128x256 per CTA,
//       shared A panel; B ring of 4x32KB buffers refilled across tiles;
//       16 warps, warp tile 32x64; mma.sync.m16n8k16.f16 -> fp32;
//       fused ex2 epilogue, per-row sums in registers across tiles.
//   k4: per-row __logf(s_all/s_pos), mean over rows with positives.
// ---------------------------------------------------------------------------

#define NB    8192
#define ND    256
#define BM    128
#define BN    256
#define KC    64
#define NCT   2                        // tiles per CTA
#define NTHR  512
#define CHUNK_ELEMS (NB * KC)          // elements per K-chunk plane

__device__ __align__(1024) __half g_e[NB * ND];   // [4][8192][64] swizzled fp16
__device__ int   g_lab[NB];
__device__ float g_sall[NB];
__device__ float g_spos[NB];

// ---- smem layout (bytes) ----------------------------------------------------
#define A_OFF      0           // 4 chunks x [128][64] fp16 swizzled = 64 KB
#define B_OFF      65536       // 4 bufs x [256][64] fp16 swizzled = 128 KB
#define LAB_OFF    196608      // 512 ints (2 tiles)
#define SALL_OFF   198656      // 128 floats
#define SPOS_OFF   199168      // 128 floats
#define CTRL_OFF   199680      // 4 mbarriers
#define SMEM_TOTAL 199808

// ---- PTX helpers ------------------------------------------------------------
__device__ __forceinline__ uint32_t smem_u32(const void* p) {
    uint32_t a;
    asm("{ .reg .u64 t; cvta.to.shared.u64 t, %1; cvt.u32.u64 %0, t; }" : "=r"(a) : "l"(p));
    return a;
}
__device__ __forceinline__ uint32_t sw128(uint32_t off) {
    return off ^ ((off >> 3) & 0x70);   // permutes 16B granules within a 128B row
}
__device__ __forceinline__ float ex2(float x) {
    float y;
    asm("ex2.approx.ftz.f32 %0, %1;" : "=f"(y) : "f"(x));
    return y;
}
#define MBAR_INIT(addr, cnt) \
    asm volatile("mbarrier.init.shared.b64 [%0], %1;" :: "r"(addr), "r"((uint32_t)(cnt)) : "memory")
#define MBAR_EXPECT_TX(addr, bytes) \
    asm volatile("mbarrier.arrive.expect_tx.shared.b64 _, [%0], %1;" :: "r"(addr), "r"((uint32_t)(bytes)) : "memory")
#define MBAR_WAIT(addr, parity) do {                                                   \
    asm volatile("{\n\t.reg .pred P1;\n\t"                                             \
        "WAIT_LP_%=:\n\t"                                                              \
        "mbarrier.try_wait.parity.acquire.cta.shared::cta.b64 P1, [%0], %1, 0x989680;\n\t" \
        "@P1 bra.uni WAIT_DN_%=;\n\t"                                                  \
        "bra.uni WAIT_LP_%=;\n\t"                                                      \
        "WAIT_DN_%=:\n\t}"                                                             \
        :: "r"(addr), "r"((uint32_t)(parity)) : "memory");                             \
} while (0)
__device__ __forceinline__ void bulk_ld(uint32_t dst, const void* src,
                                        uint32_t bytes, uint32_t mbar) {
    asm volatile(
        "cp.async.bulk.shared::cta.global.mbarrier::complete_tx::bytes [%0], [%1], %2, [%3];"
        :: "r"(dst), "l"(src), "r"(bytes), "r"(mbar) : "memory");
}
__device__ __forceinline__ void ldsm4(uint32_t* r, uint32_t addr) {
    asm volatile("ldmatrix.sync.aligned.m8n8.x4.shared.b16 {%0,%1,%2,%3}, [%4];"
        : "=r"(r[0]), "=r"(r[1]), "=r"(r[2]), "=r"(r[3]) : "r"(addr));
}
__device__ __forceinline__ void mma_f16(float* d, const uint32_t* a, const uint32_t* b) {
    asm volatile(
        "mma.sync.aligned.m16n8k16.row.col.f32.f16.f16.f32 "
        "{%0,%1,%2,%3},{%4,%5,%6,%7},{%8,%9},{%0,%1,%2,%3};"
        : "+f"(d[0]), "+f"(d[1]), "+f"(d[2]), "+f"(d[3])
        : "r"(a[0]), "r"(a[1]), "r"(a[2]), "r"(a[3]), "r"(b[0]), "r"(b[1]));
}

// ---------------------------------------------------------------------------
__global__ void convert_labels_kernel(const int* __restrict__ raw) {
    __shared__ int nz;
    if (threadIdx.x == 0) nz = 0;
    __syncthreads();
    int local = 0;
    for (int i = threadIdx.x; i < NB / 2; i += blockDim.x)
        local |= (raw[2 * i + 1] != 0);
    if (local) atomicOr(&nz, 1);
    __syncthreads();
    const bool is64 = (nz == 0);
    for (int i = threadIdx.x; i < NB; i += blockDim.x) {
        g_lab[i]  = is64 ? raw[2 * i] : raw[i];
        g_sall[i] = 0.f;
        g_spos[i] = 0.f;
    }
}

// ---------------------------------------------------------------------------
__global__ void normalize_kernel(const float* __restrict__ emb) {
    __shared__ float ws[8];
    const int r = blockIdx.x, d = threadIdx.x;
    float v  = emb[r * ND + d];
    float ss = v * v;
    #pragma unroll
    for (int off = 16; off > 0; off >>= 1)
        ss += __shfl_xor_sync(0xffffffffu, ss, off);
    if ((d & 31) == 0) ws[d >> 5] = ss;
    __syncthreads();
    float tot = ws[0] + ws[1] + ws[2] + ws[3] + ws[4] + ws[5] + ws[6] + ws[7];
    float nrm = fmaxf(sqrtf(tot), 1e-12f);
    float e   = v / nrm;

    const int kc = d >> 6, c = d & 63, k16 = c >> 3, b = c & 7;
    const uint32_t idx = (uint32_t)kc * CHUNK_ELEMS
                       + (sw128((uint32_t)r * 128 + (uint32_t)k16 * 16) >> 1) + b;
    g_e[idx] = __float2half(e);
}

// ---------------------------------------------------------------------------
__global__ void __launch_bounds__(NTHR, 1) gemm_lse_kernel() {
    extern __shared__ char smem[];
    const uint32_t sb = smem_u32(smem);
    int*   lab_sm  = (int*)(smem + LAB_OFF);
    float* sall_sm = (float*)(smem + SALL_OFF);
    float* spos_sm = (float*)(smem + SPOS_OFF);

    const int tid  = threadIdx.x;
    const int wid  = tid >> 5, lane = tid & 31;
    const int wm   = wid >> 2;           // 0..3  (32 rows each)
    const int wn   = wid & 3;            // 0..3  (64 cols each)
    const int rowbase = (int)(blockIdx.x >> 4) * BM;         // 64 strips
    const int cgbase  = (int)(blockIdx.x & 15) * (BN * NCT); // 16 col groups

    // prologue: labels (both tiles) + smem row accumulators + mbarriers
    if (tid < 512) lab_sm[tid] = g_lab[cgbase + tid];
    if (tid < BM) { sall_sm[tid] = 0.f; spos_sm[tid] = 0.f; }
    if (tid == 0) {
        #pragma unroll
        for (int kc = 0; kc < 4; ++kc) MBAR_INIT(sb + CTRL_OFF + 8 * kc, 1);
    }
    __syncthreads();
    // prefetch A chunk kc + B(tile0, kc) into buffer kc
    if (tid == 0) {
        #pragma unroll
        for (int kc = 0; kc < 4; ++kc) {
            const uint32_t mb = sb + CTRL_OFF + 8 * kc;
            const size_t ao = (size_t)kc * CHUNK_ELEMS + (size_t)rowbase * KC;
            const size_t bo = (size_t)kc * CHUNK_ELEMS + (size_t)cgbase * KC;
            MBAR_EXPECT_TX(mb, 16384 + 32768);
            bulk_ld(sb + A_OFF + kc * 16384, g_e + ao, 16384, mb);
            bulk_ld(sb + B_OFF + kc * 32768, g_e + bo, 32768, mb);
        }
    }

    // ldmatrix lane addressing constants
    const uint32_t a_row = ((lane >> 3) & 1) * 8 + (lane & 7);
    const uint32_t a_kb  = ((lane >> 4) & 1) * 16;
    const uint32_t b_row = ((lane >> 4) & 1) * 8 + (lane & 7);
    const uint32_t b_kb  = ((lane >> 3) & 1) * 16;
    const uint32_t xm    = (uint32_t)(lane & 7) << 4;
    const uint32_t arow_off = (wm * 32 + a_row) * 128;       // warp = 32 rows
    const uint32_t brow_off = (wn * 64 + b_row) * 128;

    // row labels (fixed across tiles): 4 rows per thread
    int rlab[4];
    #pragma unroll
    for (int mt = 0; mt < 2; ++mt) {
        const int r0 = rowbase + wm * 32 + mt * 16 + (lane >> 2);
        rlab[2 * mt]     = g_lab[r0];
        rlab[2 * mt + 1] = g_lab[r0 + 8];
    }

    // per-row partial sums persist across both tiles
    float psall[4], pspos[4];
    #pragma unroll
    for (int r = 0; r < 4; ++r) { psall[r] = 0.f; pspos[r] = 0.f; }

    const float C2 = 20.609929230246954f;   // log2(e)/T

    #pragma unroll
    for (int t = 0; t < NCT; ++t) {
        const int colbase = cgbase + t * BN;

        float acc[2][8][4];
        #pragma unroll
        for (int mt = 0; mt < 2; ++mt)
            #pragma unroll
            for (int nt = 0; nt < 8; ++nt)
                #pragma unroll
                for (int e = 0; e < 4; ++e) acc[mt][nt][e] = 0.f;

        #pragma unroll
        for (int kc = 0; kc < ND / KC; ++kc) {       // 4 chunks
            MBAR_WAIT(sb + CTRL_OFF + 8 * kc, t & 1);
            const uint32_t sa   = sb + A_OFF + kc * 16384;
            const uint32_t sbuf = sb + B_OFF + kc * 32768;
            #pragma unroll
            for (int k16 = 0; k16 < 4; ++k16) {
                const uint32_t akx = ((uint32_t)(k16 * 32) + a_kb) ^ xm;
                const uint32_t bkx = ((uint32_t)(k16 * 32) + b_kb) ^ xm;
                uint32_t ah[2][4], bh[4][4];
                #pragma unroll
                for (int mt = 0; mt < 2; ++mt)
                    ldsm4(ah[mt], sa + arow_off + mt * 2048 + akx);
                #pragma unroll
                for (int p = 0; p < 4; ++p)
                    ldsm4(bh[p], sbuf + brow_off + p * 2048 + bkx);
                #pragma unroll
                for (int mt = 0; mt < 2; ++mt)
                    #pragma unroll
                    for (int nt = 0; nt < 8; ++nt)
                        mma_f16(acc[mt][nt], ah[mt], &bh[nt >> 1][(nt & 1) * 2]);
            }
            if (t < NCT - 1) {
                __syncthreads();                     // all warps done with buf kc
                if (tid == 0) {                      // refill with next tile's B
                    const uint32_t mb = sb + CTRL_OFF + 8 * kc;
                    const size_t bo = (size_t)kc * CHUNK_ELEMS
                                    + (size_t)(colbase + BN) * KC;
                    MBAR_EXPECT_TX(mb, 32768);
                    bulk_ld(sb + B_OFF + kc * 32768, g_e + bo, 32768, mb);
                }
            }
        }

        // ---- fused epilogue for tile t (overlaps tile t+1's DMA) ----
        const bool has_diag = (rowbase >> 8) == (colbase >> 8);
        const int  lbase    = t * 256 + wn * 64 + 2 * (lane & 3);

        #pragma unroll
        for (int mt = 0; mt < 2; ++mt) {
            const int rg0 = rowbase + wm * 32 + mt * 16 + (lane >> 2);
            const int rg1 = rg0 + 8;
            #pragma unroll
            for (int nt = 0; nt < 8; ++nt) {
                const int lc0 = lab_sm[lbase + nt * 8];
                const int lc1 = lab_sm[lbase + nt * 8 + 1];
                const float* a4 = acc[mt][nt];
                float v0 = ex2(fmaf(a4[0], C2, -C2));
                float v1 = ex2(fmaf(a4[1], C2, -C2));
                float v2 = ex2(fmaf(a4[2], C2, -C2));
                float v3 = ex2(fmaf(a4[3], C2, -C2));
                if (has_diag) {
                    const int cg0 = colbase + wn * 64 + nt * 8 + 2 * (lane & 3);
                    const int cg1 = cg0 + 1;
                    if (rg0 == cg0) v0 = 0.f;
                    if (rg0 == cg1) v1 = 0.f;
                    if (rg1 == cg0) v2 = 0.f;
                    if (rg1 == cg1) v3 = 0.f;
                }
                psall[2 * mt]     += v0 + v1;
                psall[2 * mt + 1] += v2 + v3;
                if (lc0 == rlab[2 * mt])     pspos[2 * mt]     += v0;
                if (lc1 == rlab[2 * mt])     pspos[2 * mt]     += v1;
                if (lc0 == rlab[2 * mt + 1]) pspos[2 * mt + 1] += v2;
                if (lc1 == rlab[2 * mt + 1]) pspos[2 * mt + 1] += v3;
            }
        }
    }

    // ---- flush per-row sums: smem once, then global once ----
    #pragma unroll
    for (int mt = 0; mt < 2; ++mt) {
        const int rl0 = wm * 32 + mt * 16 + (lane >> 2);
        atomicAdd(&sall_sm[rl0],     psall[2 * mt]);
        atomicAdd(&sall_sm[rl0 + 8], psall[2 * mt + 1]);
        atomicAdd(&spos_sm[rl0],     pspos[2 * mt]);
        atomicAdd(&spos_sm[rl0 + 8], pspos[2 * mt + 1]);
    }
    __syncthreads();
    if (tid < BM) {
        atomicAdd(&g_sall[rowbase + tid], sall_sm[tid]);
        atomicAdd(&g_spos[rowbase + tid], spos_sm[tid]);
    }
}

// ---------------------------------------------------------------------------
__global__ void finalize_kernel(float* __restrict__ out) {
    __shared__ float ssum[32];
    __shared__ int   scnt[32];
    const int tid = threadIdx.x, w = tid >> 5, l = tid & 31;
    float sp[8], sa[8];
    #pragma unroll
    for (int i = 0; i < 8; ++i) {
        sp[i] = g_spos[tid + 1024 * i];
        sa[i] = g_sall[tid + 1024 * i];
    }
    float ls = 0.f; int lc = 0;
    #pragma unroll
    for (int i = 0; i < 8; ++i) {
        if (sp[i] > 0.f) { ls += __logf(sa[i] / sp[i]); lc++; }
    }
    #pragma unroll
    for (int off = 16; off > 0; off >>= 1) {
        ls += __shfl_xor_sync(0xffffffffu, ls, off);
        lc += __shfl_xor_sync(0xffffffffu, lc, off);
    }
    if (l == 0) { ssum[w] = ls; scnt[w] = lc; }
    __syncthreads();
    if (w == 0) {
        ls = ssum[l]; lc = scnt[l];
        #pragma unroll
        for (int off = 16; off > 0; off >>= 1) {
            ls += __shfl_xor_sync(0xffffffffu, ls, off);
            lc += __shfl_xor_sync(0xffffffffu, lc, off);
        }
        if (l == 0) out[0] = (lc > 0) ? (ls / (float)lc) : 0.0f;
    }
}

// ---------------------------------------------------------------------------
extern "C" void kernel_launch(void* const* d_in, const int* in_sizes, int n_in,
                              void* d_out, int out_size) {
    const float* emb = (const float*)d_in[0];
    const int*   lab = (const int*)d_in[1];
    float*       out = (float*)d_out;

    cudaFuncSetAttribute(gemm_lse_kernel,
                         cudaFuncAttributeMaxDynamicSharedMemorySize, SMEM_TOTAL);

    convert_labels_kernel<<<1, 1024>>>(lab);
    normalize_kernel<<<NB, ND>>>(emb);
    gemm_lse_kernel<<<(NB / BM) * (NB / (BN * NCT)), NTHR, SMEM_TOTAL>>>();
    finalize_kernel<<<1, 1024>>>(out);
}

// round 15
// speedup vs baseline: 8.9344x; 1.4511x over previous
#include <cuda_runtime.h>
#include <cuda_fp16.h>
#include <cstdint>

// ---------------------------------------------------------------------------
// InfoNCE supervised-contrastive loss — SYMMETRIC strip-pair fp16 HMMA.
// sim = e.eT is symmetric: compute each 128x128 strip-pair tile ONCE
// (2080 jobs = 2016 upper-triangle + 64 diagonal), use it for BOTH
// row sums (strip p) and column sums (strip q).
//   k1: label width detect (i64/i32) -> i32; zero row accumulators
//   k2: normalize rows (warp/row, vectorized), store fp16 K-chunk-major,
//       PRE-SWIZZLED (SW128) so linear bulk copies land MMA-ready in smem.
//   k3: 2080 CTAs x 256 thr (2 CTAs/SM), 8 warps, warp tile 32x64,
//       A/B chunk rings fed by cp.async.bulk; mma.sync.m16n8k16.f16;
//       fused ex2 epilogue -> row sums + shfl-reduced column sums.
//   k4: per-row __logf(s_all/s_pos), mean over rows with positives.
// ---------------------------------------------------------------------------

#define NB      8192
#define ND      256
#define SROWS   128                    // strip size
#define NSTRIP  64
#define NJOBS   (NSTRIP * (NSTRIP + 1) / 2)   // 2080
#define KC      64
#define NTHR    256
#define CHUNK_ELEMS (NB * KC)          // elements per K-chunk plane

__device__ __align__(1024) __half g_e[NB * ND];   // [4][8192][64] swizzled fp16
__device__ int   g_lab[NB];
__device__ float g_sall[NB];
__device__ float g_spos[NB];

// ---- smem layout (bytes) ----------------------------------------------------
#define A_OFF      0           // 3 slots x [128][64] fp16 swizzled = 48 KB
#define B_OFF      49152       // 3 slots x [128][64] fp16 swizzled = 48 KB
#define LABP_OFF   98304       // 128 ints
#define LABQ_OFF   98816       // 128 ints
#define RSALL_OFF  99328       // 128 floats
#define RSPOS_OFF  99840
#define CSALL_OFF  100352
#define CSPOS_OFF  100864
#define CTRL_OFF   101376      // 3 mbarriers
#define SMEM_TOTAL 101408

// ---- PTX helpers ------------------------------------------------------------
__device__ __forceinline__ uint32_t smem_u32(const void* p) {
    uint32_t a;
    asm("{ .reg .u64 t; cvta.to.shared.u64 t, %1; cvt.u32.u64 %0, t; }" : "=r"(a) : "l"(p));
    return a;
}
__device__ __forceinline__ uint32_t sw128(uint32_t off) {
    return off ^ ((off >> 3) & 0x70);
}
__device__ __forceinline__ float ex2(float x) {
    float y;
    asm("ex2.approx.ftz.f32 %0, %1;" : "=f"(y) : "f"(x));
    return y;
}
#define MBAR_INIT(addr, cnt) \
    asm volatile("mbarrier.init.shared.b64 [%0], %1;" :: "r"(addr), "r"((uint32_t)(cnt)) : "memory")
#define MBAR_EXPECT_TX(addr, bytes) \
    asm volatile("mbarrier.arrive.expect_tx.shared.b64 _, [%0], %1;" :: "r"(addr), "r"((uint32_t)(bytes)) : "memory")
#define MBAR_WAIT(addr, parity) do {                                                   \
    asm volatile("{\n\t.reg .pred P1;\n\t"                                             \
        "WAIT_LP_%=:\n\t"                                                              \
        "mbarrier.try_wait.parity.acquire.cta.shared::cta.b64 P1, [%0], %1, 0x989680;\n\t" \
        "@P1 bra.uni WAIT_DN_%=;\n\t"                                                  \
        "bra.uni WAIT_LP_%=;\n\t"                                                      \
        "WAIT_DN_%=:\n\t}"                                                             \
        :: "r"(addr), "r"((uint32_t)(parity)) : "memory");                             \
} while (0)
__device__ __forceinline__ void bulk_ld(uint32_t dst, const void* src,
                                        uint32_t bytes, uint32_t mbar) {
    asm volatile(
        "cp.async.bulk.shared::cta.global.mbarrier::complete_tx::bytes [%0], [%1], %2, [%3];"
        :: "r"(dst), "l"(src), "r"(bytes), "r"(mbar) : "memory");
}
__device__ __forceinline__ void ldsm4(uint32_t* r, uint32_t addr) {
    asm volatile("ldmatrix.sync.aligned.m8n8.x4.shared.b16 {%0,%1,%2,%3}, [%4];"
        : "=r"(r[0]), "=r"(r[1]), "=r"(r[2]), "=r"(r[3]) : "r"(addr));
}
__device__ __forceinline__ void mma_f16(float* d, const uint32_t* a, const uint32_t* b) {
    asm volatile(
        "mma.sync.aligned.m16n8k16.row.col.f32.f16.f16.f32 "
        "{%0,%1,%2,%3},{%4,%5,%6,%7},{%8,%9},{%0,%1,%2,%3};"
        : "+f"(d[0]), "+f"(d[1]), "+f"(d[2]), "+f"(d[3])
        : "r"(a[0]), "r"(a[1]), "r"(a[2]), "r"(a[3]), "r"(b[0]), "r"(b[1]));
}

// ---------------------------------------------------------------------------
__global__ void convert_labels_kernel(const int* __restrict__ raw) {
    __shared__ int nz;
    if (threadIdx.x == 0) nz = 0;
    __syncthreads();
    int local = 0;
    for (int i = threadIdx.x; i < NB / 2; i += blockDim.x)
        local |= (raw[2 * i + 1] != 0);
    if (local) atomicOr(&nz, 1);
    __syncthreads();
    const bool is64 = (nz == 0);
    for (int i = threadIdx.x; i < NB; i += blockDim.x) {
        g_lab[i]  = is64 ? raw[2 * i] : raw[i];
        g_sall[i] = 0.f;
        g_spos[i] = 0.f;
    }
}

// ---------------------------------------------------------------------------
// One warp per row: vectorized load, warp reduce, packed 16B swizzled store.
__global__ void normalize_kernel(const float* __restrict__ emb) {
    const int w = threadIdx.x >> 5, lane = threadIdx.x & 31;
    const int r = blockIdx.x * 8 + w;
    const float4 x0 = *(const float4*)(emb + r * ND + lane * 8);
    const float4 x1 = *(const float4*)(emb + r * ND + lane * 8 + 4);
    float ss = x0.x * x0.x + x0.y * x0.y + x0.z * x0.z + x0.w * x0.w
             + x1.x * x1.x + x1.y * x1.y + x1.z * x1.z + x1.w * x1.w;
    #pragma unroll
    for (int off = 16; off > 0; off >>= 1)
        ss += __shfl_xor_sync(0xffffffffu, ss, off);
    const float rn = 1.0f / fmaxf(sqrtf(ss), 1e-12f);

    union { uint4 u; __half h[8]; } pk;
    pk.h[0] = __float2half(x0.x * rn); pk.h[1] = __float2half(x0.y * rn);
    pk.h[2] = __float2half(x0.z * rn); pk.h[3] = __float2half(x0.w * rn);
    pk.h[4] = __float2half(x1.x * rn); pk.h[5] = __float2half(x1.y * rn);
    pk.h[6] = __float2half(x1.z * rn); pk.h[7] = __float2half(x1.w * rn);

    const int kc = lane >> 3, k16 = lane & 7;       // d = lane*8 .. +7
    __half* dst = g_e + (uint32_t)kc * CHUNK_ELEMS
                + (sw128((uint32_t)r * 128 + (uint32_t)k16 * 16) >> 1);
    *(uint4*)dst = pk.u;
}

// ---------------------------------------------------------------------------
__global__ void __launch_bounds__(NTHR, 2) gemm_lse_kernel() {
    extern __shared__ char smem[];
    const uint32_t sb = smem_u32(smem);
    int*   labp = (int*)(smem + LABP_OFF);
    int*   labq = (int*)(smem + LABQ_OFF);
    float* rsall = (float*)(smem + RSALL_OFF);
    float* rspos = (float*)(smem + RSPOS_OFF);
    float* csall = (float*)(smem + CSALL_OFF);
    float* cspos = (float*)(smem + CSPOS_OFF);

    const int tid = threadIdx.x, wid = tid >> 5, lane = tid & 31;
    const int wm = wid >> 1;             // 0..3 (32 rows each)
    const int wn = wid & 1;              // 0..1 (64 cols each)

    // ---- decode job -> strip pair (p <= q) ----
    const int j = (int)blockIdx.x;
    int p = (int)((129.0f - sqrtf(16641.0f - 8.0f * (float)j)) * 0.5f);
    while (p > 0 && p * (129 - p) / 2 > j) --p;
    while ((p + 1) * (129 - (p + 1)) / 2 <= j) ++p;
    const int q = p + (j - p * (129 - p) / 2);
    const bool isdiag = (p == q);
    const int prow = p * SROWS, qrow = q * SROWS;

    // ---- prologue: labels + accumulators + barriers ----
    if (tid < 128) {
        labp[tid] = g_lab[prow + tid];
        rsall[tid] = 0.f; rspos[tid] = 0.f;
    } else {
        const int t = tid - 128;
        labq[t] = g_lab[qrow + t];
        csall[t] = 0.f; cspos[t] = 0.f;
    }
    if (tid == 0) {
        #pragma unroll
        for (int s = 0; s < 3; ++s) MBAR_INIT(sb + CTRL_OFF + 8 * s, 1);
    }
    __syncthreads();
    if (tid == 0) {
        #pragma unroll
        for (int kc = 0; kc < 3; ++kc) {
            const uint32_t mb = sb + CTRL_OFF + 8 * kc;
            MBAR_EXPECT_TX(mb, 32768);
            bulk_ld(sb + A_OFF + kc * 16384,
                    g_e + (size_t)kc * CHUNK_ELEMS + (size_t)prow * KC, 16384, mb);
            bulk_ld(sb + B_OFF + kc * 16384,
                    g_e + (size_t)kc * CHUNK_ELEMS + (size_t)qrow * KC, 16384, mb);
        }
    }

    // ldmatrix lane addressing constants
    const uint32_t a_row = ((lane >> 3) & 1) * 8 + (lane & 7);
    const uint32_t a_kb  = ((lane >> 4) & 1) * 16;
    const uint32_t b_row = ((lane >> 4) & 1) * 8 + (lane & 7);
    const uint32_t b_kb  = ((lane >> 3) & 1) * 16;
    const uint32_t xm    = (uint32_t)(lane & 7) << 4;
    const uint32_t arow_off = (wm * 32 + a_row) * 128;
    const uint32_t brow_off = (wn * 64 + b_row) * 128;

    float acc[2][8][4];
    #pragma unroll
    for (int mt = 0; mt < 2; ++mt)
        #pragma unroll
        for (int nt = 0; nt < 8; ++nt)
            #pragma unroll
            for (int e = 0; e < 4; ++e) acc[mt][nt][e] = 0.f;

    #pragma unroll
    for (int kc = 0; kc < ND / KC; ++kc) {           // 4 chunks, ring of 3
        const int slot = (kc < 3) ? kc : 0;
        MBAR_WAIT(sb + CTRL_OFF + 8 * slot, (kc < 3) ? 0 : 1);
        const uint32_t sa   = sb + A_OFF + slot * 16384;
        const uint32_t sbuf = sb + B_OFF + slot * 16384;
        #pragma unroll
        for (int k16 = 0; k16 < 4; ++k16) {
            const uint32_t akx = ((uint32_t)(k16 * 32) + a_kb) ^ xm;
            const uint32_t bkx = ((uint32_t)(k16 * 32) + b_kb) ^ xm;
            uint32_t ah[2][4], bh[4][4];
            #pragma unroll
            for (int mt = 0; mt < 2; ++mt)
                ldsm4(ah[mt], sa + arow_off + mt * 2048 + akx);
            #pragma unroll
            for (int pp = 0; pp < 4; ++pp)
                ldsm4(bh[pp], sbuf + brow_off + pp * 2048 + bkx);
            #pragma unroll
            for (int mt = 0; mt < 2; ++mt)
                #pragma unroll
                for (int nt = 0; nt < 8; ++nt)
                    mma_f16(acc[mt][nt], ah[mt], &bh[nt >> 1][(nt & 1) * 2]);
        }
        if (kc == 0) {                               // refill slot 0 with chunk 3
            __syncthreads();
            if (tid == 0) {
                const uint32_t mb = sb + CTRL_OFF;
                MBAR_EXPECT_TX(mb, 32768);
                bulk_ld(sb + A_OFF,
                        g_e + (size_t)3 * CHUNK_ELEMS + (size_t)prow * KC, 16384, mb);
                bulk_ld(sb + B_OFF,
                        g_e + (size_t)3 * CHUNK_ELEMS + (size_t)qrow * KC, 16384, mb);
            }
        }
    }

    // ================= fused epilogue: rows (p) AND columns (q) ==============
    const float C2 = 20.609929230246954f;   // log2(e)/T
    const int rlb = wm * 32 + (lane >> 2);  // local rows: rlb + {0,8,16,24}
    int rlab[4];
    rlab[0] = labp[rlb];      rlab[1] = labp[rlb + 8];
    rlab[2] = labp[rlb + 16]; rlab[3] = labp[rlb + 24];

    float psall[4] = {0.f, 0.f, 0.f, 0.f};
    float pspos[4] = {0.f, 0.f, 0.f, 0.f};
    float colall[16], colpos[16];

    #pragma unroll
    for (int nt = 0; nt < 8; ++nt) {
        const int cl0 = wn * 64 + nt * 8 + 2 * (lane & 3);
        const int cl1 = cl0 + 1;
        const int lc0 = labq[cl0], lc1 = labq[cl1];
        float ca0 = 0.f, ca1 = 0.f, cp0 = 0.f, cp1 = 0.f;
        #pragma unroll
        for (int mt = 0; mt < 2; ++mt) {
            const int rl0 = rlb + mt * 16;
            const int rl1 = rl0 + 8;
            const float* a4 = acc[mt][nt];
            float v0 = ex2(fmaf(a4[0], C2, -C2));
            float v1 = ex2(fmaf(a4[1], C2, -C2));
            float v2 = ex2(fmaf(a4[2], C2, -C2));
            float v3 = ex2(fmaf(a4[3], C2, -C2));
            if (isdiag) {
                if (rl0 == cl0) v0 = 0.f;
                if (rl0 == cl1) v1 = 0.f;
                if (rl1 == cl0) v2 = 0.f;
                if (rl1 == cl1) v3 = 0.f;
            }
            psall[2 * mt]     += v0 + v1;
            psall[2 * mt + 1] += v2 + v3;
            ca0 += v0 + v2;
            ca1 += v1 + v3;
            if (lc0 == rlab[2 * mt])     { pspos[2 * mt]     += v0; cp0 += v0; }
            if (lc1 == rlab[2 * mt])     { pspos[2 * mt]     += v1; cp1 += v1; }
            if (lc0 == rlab[2 * mt + 1]) { pspos[2 * mt + 1] += v2; cp0 += v2; }
            if (lc1 == rlab[2 * mt + 1]) { pspos[2 * mt + 1] += v3; cp1 += v3; }
        }
        colall[2 * nt] = ca0; colall[2 * nt + 1] = ca1;
        colpos[2 * nt] = cp0; colpos[2 * nt + 1] = cp1;
    }

    // ---- row flush to smem ----
    atomicAdd(&rsall[rlb],      psall[0]);
    atomicAdd(&rsall[rlb + 8],  psall[1]);
    atomicAdd(&rsall[rlb + 16], psall[2]);
    atomicAdd(&rsall[rlb + 24], psall[3]);
    atomicAdd(&rspos[rlb],      pspos[0]);
    atomicAdd(&rspos[rlb + 8],  pspos[1]);
    atomicAdd(&rspos[rlb + 16], pspos[2]);
    atomicAdd(&rspos[rlb + 24], pspos[3]);

    // ---- column reduce across the 8 row-lanes (same lane&3), then smem ----
    if (!isdiag) {
        #pragma unroll
        for (int i = 0; i < 16; ++i) {
            #pragma unroll
            for (int off = 4; off <= 16; off <<= 1) {
                colall[i] += __shfl_xor_sync(0xffffffffu, colall[i], off);
                colpos[i] += __shfl_xor_sync(0xffffffffu, colpos[i], off);
            }
        }
        if (lane < 4) {
            #pragma unroll
            for (int nt = 0; nt < 8; ++nt) {
                const int c0 = wn * 64 + nt * 8 + 2 * lane;
                atomicAdd(&csall[c0],     colall[2 * nt]);
                atomicAdd(&csall[c0 + 1], colall[2 * nt + 1]);
                atomicAdd(&cspos[c0],     colpos[2 * nt]);
                atomicAdd(&cspos[c0 + 1], colpos[2 * nt + 1]);
            }
        }
    }
    __syncthreads();

    // ---- global flush ----
    if (tid < 128) {
        atomicAdd(&g_sall[prow + tid], rsall[tid]);
        atomicAdd(&g_spos[prow + tid], rspos[tid]);
    } else if (!isdiag) {
        const int t = tid - 128;
        atomicAdd(&g_sall[qrow + t], csall[t]);
        atomicAdd(&g_spos[qrow + t], cspos[t]);
    }
}

// ---------------------------------------------------------------------------
__global__ void finalize_kernel(float* __restrict__ out) {
    __shared__ float ssum[32];
    __shared__ int   scnt[32];
    const int tid = threadIdx.x, w = tid >> 5, l = tid & 31;
    float sp[8], sa[8];
    #pragma unroll
    for (int i = 0; i < 8; ++i) {
        sp[i] = g_spos[tid + 1024 * i];
        sa[i] = g_sall[tid + 1024 * i];
    }
    float ls = 0.f; int lc = 0;
    #pragma unroll
    for (int i = 0; i < 8; ++i) {
        if (sp[i] > 0.f) { ls += __logf(sa[i] / sp[i]); lc++; }
    }
    #pragma unroll
    for (int off = 16; off > 0; off >>= 1) {
        ls += __shfl_xor_sync(0xffffffffu, ls, off);
        lc += __shfl_xor_sync(0xffffffffu, lc, off);
    }
    if (l == 0) { ssum[w] = ls; scnt[w] = lc; }
    __syncthreads();
    if (w == 0) {
        ls = ssum[l]; lc = scnt[l];
        #pragma unroll
        for (int off = 16; off > 0; off >>= 1) {
            ls += __shfl_xor_sync(0xffffffffu, ls, off);
            lc += __shfl_xor_sync(0xffffffffu, lc, off);
        }
        if (l == 0) out[0] = (lc > 0) ? (ls / (float)lc) : 0.0f;
    }
}

// ---------------------------------------------------------------------------
extern "C" void kernel_launch(void* const* d_in, const int* in_sizes, int n_in,
                              void* d_out, int out_size) {
    const float* emb = (const float*)d_in[0];
    const int*   lab = (const int*)d_in[1];
    float*       out = (float*)d_out;

    cudaFuncSetAttribute(gemm_lse_kernel,
                         cudaFuncAttributeMaxDynamicSharedMemorySize, SMEM_TOTAL);

    convert_labels_kernel<<<1, 1024>>>(lab);
    normalize_kernel<<<NB / 8, 256>>>(emb);
    gemm_lse_kernel<<<NJOBS, NTHR, SMEM_TOTAL>>>();
    finalize_kernel<<<1, 1024>>>(out);
}